// round 14
// baseline (speedup 1.0000x reference)
#include <cuda_runtime.h>
#include <cuda_bf16.h>
#include <cstdint>
#include <math.h>

#define B_SZ   4
#define C_DIM  512
#define N_DIM  512
#define S_DIM  64
#define L_DIM  8192
#define NCHK   128

typedef __nv_bfloat16 bf16;

// ---------------------------------------------------------------------------
// Scratch (allocation-free rule: __device__ globals)
// ---------------------------------------------------------------------------
__device__ __align__(128) bf16  g_inh[(size_t)B_SZ * C_DIM * L_DIM];
__device__ __align__(128) bf16  g_inl[(size_t)B_SZ * C_DIM * L_DIM];
__device__ __align__(128) bf16  g_xh [(size_t)B_SZ * N_DIM * L_DIM];
__device__ __align__(128) bf16  g_xl [(size_t)B_SZ * N_DIM * L_DIM];
__device__ __align__(128) bf16  g_yh [(size_t)B_SZ * N_DIM * L_DIM];
__device__ __align__(128) bf16  g_yl [(size_t)B_SZ * N_DIM * L_DIM];
__device__ __align__(128) bf16  g_bh [C_DIM * N_DIM];
__device__ __align__(128) bf16  g_bl [C_DIM * N_DIM];
__device__ __align__(128) bf16  g_ch [C_DIM * N_DIM];
__device__ __align__(128) bf16  g_cl [C_DIM * N_DIM];
__device__ __align__(128) bf16  g_wbh[(size_t)N_DIM * 192 * 64];
__device__ __align__(128) bf16  g_wbl[(size_t)N_DIM * 192 * 64];
__device__ __align__(128) bf16  g_wch[(size_t)N_DIM * 64 * 128];
__device__ __align__(128) bf16  g_wcl[(size_t)N_DIM * 64 * 128];

// ---------------------------------------------------------------------------
// Helpers (base PTX only)
// ---------------------------------------------------------------------------
__device__ __forceinline__ uint32_t smem_u32(const void* p) {
    uint32_t a;
    asm("{ .reg .u64 t; cvta.to.shared.u64 t, %1; cvt.u32.u64 %0, t; }" : "=r"(a) : "l"(p));
    return a;
}
__device__ __forceinline__ void cpa16(uint32_t d, const void* s) {
    asm volatile("cp.async.cg.shared.global [%0], [%1], 16;" :: "r"(d), "l"(s));
}
#define CP_COMMIT()   asm volatile("cp.async.commit_group;" ::: "memory")
#define CP_WAIT3()    asm volatile("cp.async.wait_group 3;"  ::: "memory")
#define CP_WAIT1()    asm volatile("cp.async.wait_group 1;"  ::: "memory")
#define CP_WAIT_ALL() asm volatile("cp.async.wait_group 0;" ::: "memory")

#define LDSM_X4(r0,r1,r2,r3,addr) \
    asm volatile("ldmatrix.sync.aligned.m8n8.x4.shared.b16 {%0,%1,%2,%3}, [%4];" \
        : "=r"(r0), "=r"(r1), "=r"(r2), "=r"(r3) : "r"(addr))
#define LDSM_X4T(r0,r1,r2,r3,addr) \
    asm volatile("ldmatrix.sync.aligned.m8n8.x4.trans.shared.b16 {%0,%1,%2,%3}, [%4];" \
        : "=r"(r0), "=r"(r1), "=r"(r2), "=r"(r3) : "r"(addr))

#define MMA16816(d, a, b0v, b1v) \
    asm volatile("mma.sync.aligned.m16n8k16.row.col.f32.bf16.bf16.f32 " \
        "{%0,%1,%2,%3}, {%4,%5,%6,%7}, {%8,%9}, {%0,%1,%2,%3};" \
        : "+f"((d)[0]), "+f"((d)[1]), "+f"((d)[2]), "+f"((d)[3]) \
        : "r"((a)[0]), "r"((a)[1]), "r"((a)[2]), "r"((a)[3]), "r"(b0v), "r"(b1v))

__device__ __forceinline__ void split1(float v, bf16& h, bf16& l) {
    h = __float2bfloat16_rn(v);
    l = __float2bfloat16_rn(v - __bfloat162float(h));
}

// ---------------------------------------------------------------------------
// Combined split pre-pass: one launch splits input, Bm, Cm.
// ---------------------------------------------------------------------------
#define SPLIT_IN_BLOCKS  (B_SZ * C_DIM * L_DIM / 1024)   // 16384
#define SPLIT_W_BLOCKS   (C_DIM * N_DIM / 1024)          // 256
#define SPLIT_GRID       (SPLIT_IN_BLOCKS + 2 * SPLIT_W_BLOCKS)

__global__ __launch_bounds__(256) void split_all(
    const float* __restrict__ inp, const float* __restrict__ Bm, const float* __restrict__ Cm,
    bf16* __restrict__ inh, bf16* __restrict__ inl,
    bf16* __restrict__ bh, bf16* __restrict__ bl,
    bf16* __restrict__ ch, bf16* __restrict__ cl)
{
    const int blk = blockIdx.x;
    const float* src;
    bf16 *hi, *lo;
    int base;
    if (blk < SPLIT_IN_BLOCKS) {
        src = inp; hi = inh; lo = inl; base = blk;
    } else if (blk < SPLIT_IN_BLOCKS + SPLIT_W_BLOCKS) {
        src = Bm;  hi = bh;  lo = bl;  base = blk - SPLIT_IN_BLOCKS;
    } else {
        src = Cm;  hi = ch;  lo = cl;  base = blk - SPLIT_IN_BLOCKS - SPLIT_W_BLOCKS;
    }
    int i = (base * 256 + threadIdx.x) * 4;
    float4 v = *(const float4*)(src + i);
    bf16 h0, l0, h1, l1, h2, l2, h3, l3;
    split1(v.x, h0, l0); split1(v.y, h1, l1);
    split1(v.z, h2, l2); split1(v.w, h3, l3);
    ((__nv_bfloat162*)(hi + i))[0] = __nv_bfloat162(h0, h1);
    ((__nv_bfloat162*)(hi + i))[1] = __nv_bfloat162(h2, h3);
    ((__nv_bfloat162*)(lo + i))[0] = __nv_bfloat162(l0, l1);
    ((__nv_bfloat162*)(lo + i))[1] = __nv_bfloat162(l2, l3);
}

// ---------------------------------------------------------------------------
// HMMA GEMM: Out[b] = W(512x512) @ X[b](512x8192)
// 5-stage cp.async ring, wait_group 3 (3 tiles in flight).
// ---------------------------------------------------------------------------
#define STAGE   18432
#define A_BYTES 10240
#define NCHUNK  48
#define NSTAGES 5
#define GEMM_SMEM (NSTAGES * STAGE)

__global__ __launch_bounds__(256, 2) void hgemm(
    const bf16* __restrict__ Ah, const bf16* __restrict__ Al,
    const bf16* __restrict__ Bh0, const bf16* __restrict__ Bl0,
    float* __restrict__ OutF, bf16* __restrict__ OutH, bf16* __restrict__ OutL)
{
    extern __shared__ char smem[];
    const uint32_t sb = smem_u32(smem);
    const int tid  = threadIdx.x;
    const int lane = tid & 31, wid = tid >> 5;
    const int n0 = blockIdx.x * 128;
    const int m0 = blockIdx.y * 128;
    const size_t boff = (size_t)blockIdx.z * C_DIM * L_DIM;
    const bf16* Bh = Bh0 + boff;
    const bf16* Bl = Bl0 + boff;

    const int am = tid >> 2, ac = tid & 3;
    const int bk = tid >> 4, bc = tid & 15;

    auto load_stage = [&](int cl, int st) {
        if (cl < NCHUNK) {
            const bf16* As = (cl < 32) ? Ah : Al;
            const bf16* Bs = (cl >= 16 && cl < 32) ? Bl : Bh;
            const int k0 = (cl & 15) << 5;
            const uint32_t s0 = sb + (uint32_t)st * STAGE;
            cpa16(s0 + am * 80 + ac * 16,
                  As + (size_t)(m0 + am) * C_DIM + k0 + ac * 8);
            cpa16(s0 + (am + 64) * 80 + ac * 16,
                  As + (size_t)(m0 + am + 64) * C_DIM + k0 + ac * 8);
            {
                int c1 = (bc & 8) | ((bc ^ (bk & 7)) & 7);
                cpa16(s0 + A_BYTES + bk * 256 + c1 * 16,
                      Bs + (size_t)(k0 + bk) * L_DIM + n0 + bc * 8);
                int k2 = bk + 16;
                int c2 = (bc & 8) | ((bc ^ (k2 & 7)) & 7);
                cpa16(s0 + A_BYTES + k2 * 256 + c2 * 16,
                      Bs + (size_t)(k0 + k2) * L_DIM + n0 + bc * 8);
            }
        }
        CP_COMMIT();
    };

    const int wm = (wid >> 2) * 64;
    const int wn = (wid & 3) * 32;
    const uint32_t a_base = (uint32_t)(wm + (lane & 15)) * 80 + ((lane >> 4) * 16);
    uint32_t b_off[2];
#pragma unroll
    for (int nt = 0; nt < 2; nt++) {
        int g  = (wn >> 3) + nt * 2 + (lane >> 4);
        int gp = (g & 8) | ((g ^ (lane & 7)) & 7);
        b_off[nt] = (uint32_t)(lane & 15) * 256 + gp * 16;
    }

    float acc[4][4][4];
#pragma unroll
    for (int mt = 0; mt < 4; mt++)
#pragma unroll
        for (int j = 0; j < 4; j++)
#pragma unroll
            for (int r = 0; r < 4; r++) acc[mt][j][r] = 0.f;

    load_stage(0, 0); load_stage(1, 1); load_stage(2, 2); load_stage(3, 3);

    int cs = 0;   // stage of current compute chunk
    int ls = 4;   // stage to fill next
    for (int c = 0; c < NCHUNK; c++) {
        CP_WAIT3();
        __syncthreads();
        load_stage(c + 4, ls);
        if (++ls == NSTAGES) ls = 0;

        const uint32_t Abase = sb + (uint32_t)cs * STAGE;
        const uint32_t Bbase = Abase + A_BYTES;
        if (++cs == NSTAGES) cs = 0;
#pragma unroll
        for (int kh = 0; kh < 2; kh++) {
            uint32_t a[4][4], b[2][4];
#pragma unroll
            for (int mt = 0; mt < 4; mt++)
                LDSM_X4(a[mt][0], a[mt][1], a[mt][2], a[mt][3],
                        Abase + a_base + mt * (16 * 80) + kh * 32);
#pragma unroll
            for (int nt = 0; nt < 2; nt++)
                LDSM_X4T(b[nt][0], b[nt][1], b[nt][2], b[nt][3],
                         Bbase + b_off[nt] + kh * 4096);
#pragma unroll
            for (int mt = 0; mt < 4; mt++) {
                MMA16816(acc[mt][0], a[mt], b[0][0], b[0][1]);
                MMA16816(acc[mt][1], a[mt], b[0][2], b[0][3]);
                MMA16816(acc[mt][2], a[mt], b[1][0], b[1][1]);
                MMA16816(acc[mt][3], a[mt], b[1][2], b[1][3]);
            }
        }
    }

    const int er = lane >> 2, ec = (lane & 3) * 2;
    const size_t outz = (size_t)blockIdx.z * N_DIM * L_DIM;
#pragma unroll
    for (int mt = 0; mt < 4; mt++) {
#pragma unroll
        for (int j = 0; j < 4; j++) {
            size_t base = outz + (size_t)(m0 + wm + mt * 16 + er) * L_DIM + (n0 + wn + j * 8 + ec);
            if (OutF) {
                *(float2*)&OutF[base]             = make_float2(acc[mt][j][0], acc[mt][j][1]);
                *(float2*)&OutF[base + 8 * L_DIM] = make_float2(acc[mt][j][2], acc[mt][j][3]);
            } else {
                bf16 h0, l0, h1, l1;
                split1(acc[mt][j][0], h0, l0); split1(acc[mt][j][1], h1, l1);
                *(__nv_bfloat162*)&OutH[base] = __nv_bfloat162(h0, h1);
                *(__nv_bfloat162*)&OutL[base] = __nv_bfloat162(l0, l1);
                split1(acc[mt][j][2], h0, l0); split1(acc[mt][j][3], h1, l1);
                *(__nv_bfloat162*)&OutH[base + 8 * L_DIM] = __nv_bfloat162(h0, h1);
                *(__nv_bfloat162*)&OutL[base + 8 * L_DIM] = __nv_bfloat162(l0, l1);
            }
        }
    }
}

// ---------------------------------------------------------------------------
// Prep (parallel, closed-form) — proven 20us
// ---------------------------------------------------------------------------
#define PW_WB_OFF 0
#define PW_WC_OFF (192 * 65)
#define PW_P_OFF  (PW_WC_OFF + 64 * 128)
#define PW_K_OFF  (PW_P_OFF + 64 * 65)
#define PW_SMEM   ((PW_K_OFF + 64) * 4)

__global__ __launch_bounds__(256) void prep_weights(
    const float* __restrict__ Ar, const float* __restrict__ Ai,
    const float* __restrict__ Ew,
    bf16* __restrict__ wbh, bf16* __restrict__ wbl,
    bf16* __restrict__ wch, bf16* __restrict__ wcl)
{
    extern __shared__ float sm[];
    float* sWb = sm + PW_WB_OFF;
    float* sWc = sm + PW_WC_OFF;
    float* sP  = sm + PW_P_OFF;
    float* sK  = sm + PW_K_OFF;

    const int n = blockIdx.x;
    const int tid = threadIdx.x;
    const int s = tid & 63;
    const int dg = tid >> 6;

    const float a = Ar[n * 64 + s], w = Ai[n * 64 + s], E = Ew[n * 64 + s];
    const float er = expf(a);
    const float lr = er * cosf(w), li = er * sinf(w);

#pragma unroll
    for (int dd = 0; dd < 16; dd++) {
        const int d = dg * 16 + dd;
        const float fd = (float)d;
        const float p  = expf(fd * a);
        const float cr = p * cosf(fd * w);
        const float ci = p * sinf(fd * w);
        sWc[(63 - d) * 128 + 2 * s]     = cr;
        sWc[(63 - d) * 128 + 2 * s + 1] = ci;
        sP[d * 65 + s] = E * cr;
        const float cr1 = cr * lr - ci * li;
        const float ci1 = cr * li + ci * lr;
        sWb[(64 + 2 * s) * 65 + d] = E * cr1;
        sWb[(65 + 2 * s) * 65 + d] = -E * ci1;
    }
    __syncthreads();
    if (tid < 64) {
        float acc = 0.f;
#pragma unroll
        for (int q = 0; q < 64; q++) acc += sP[tid * 65 + q];
        sK[tid] = acc;
    }
    __syncthreads();
    for (int i = tid; i < 64 * 64; i += 256) {
        int k = i >> 6, t = i & 63;
        sWb[k * 65 + t] = (t >= k) ? sK[t - k] : 0.f;
    }
    __syncthreads();
    {
        bf16* dh = wbh + (size_t)n * 192 * 64;
        bf16* dl = wbl + (size_t)n * 192 * 64;
        for (int i = tid; i < 192 * 64; i += 256) {
            int r = i >> 6, t = i & 63;
            bf16 h, l; split1(sWb[r * 65 + t], h, l);
            dh[i] = h; dl[i] = l;
        }
    }
    {
        bf16* dh = wch + (size_t)n * 64 * 128;
        bf16* dl = wcl + (size_t)n * 64 * 128;
        for (int i = tid; i < 64 * 128; i += 256) {
            bf16 h, l; split1(sWc[i], h, l);
            dh[i] = h; dl[i] = l;
        }
    }
}

// ---------------------------------------------------------------------------
// FUSED middle kernel (R13 exact): 256 threads, 4-segment parallel scan,
// Wb load overlapped behind phase 1 + scan.
// ---------------------------------------------------------------------------
#define FK_PANEL   10320
#define FK_PX_OFF  0
#define FK_PH_OFF  (4 * FK_PANEL)
#define FK_WC_OFF  (12 * FK_PANEL)
#define FK_WB_OFF  (FK_WC_OFF + 32768)
#define FK_END_OFF (FK_WB_OFF + 49152)
#define FK_SMEM    (FK_END_OFF + 2048)

__global__ __launch_bounds__(256, 1) void fused_mid(
    const bf16* __restrict__ Xh, const bf16* __restrict__ Xl,
    const bf16* __restrict__ Wch, const bf16* __restrict__ Wcl,
    const bf16* __restrict__ Wbh, const bf16* __restrict__ Wbl,
    const float* __restrict__ Ar, const float* __restrict__ Ai,
    bf16* __restrict__ Yh, bf16* __restrict__ Yl)
{
    extern __shared__ char smem[];
    const uint32_t sb = smem_u32(smem);
    const int tid  = threadIdx.x;
    const int lane = tid & 31, wid = tid >> 5;
    const int bb = blockIdx.x;
    const int n  = blockIdx.y;
    const size_t chain = (size_t)bb * N_DIM + n;

    // ---- group 0: x + Wc ------------------------------------------------
    for (int t = 0; t < 2; t++) {
        const bf16* src = (t == 0) ? (Xh + chain * L_DIM) : (Xl + chain * L_DIM);
        for (int q = tid; q < 1024; q += 256) {
            int j = q >> 3, c = q & 7;
            uint32_t dst = sb + FK_PX_OFF + (uint32_t)(t * 2 + (c >> 2)) * FK_PANEL
                         + j * 80 + (c & 3) * 16;
            cpa16(dst, src + (size_t)j * 64 + c * 8);
        }
    }
    for (int t = 0; t < 2; t++) {
        const bf16* src = ((t == 0) ? Wch : Wcl) + (size_t)n * 64 * 128;
        for (int q = tid; q < 1024; q += 256) {
            int r = q >> 4, c = q & 15;
            int cp = (c & 8) | ((c ^ (r & 7)) & 7);
            cpa16(sb + FK_WC_OFF + t * 16384 + r * 256 + cp * 16,
                  src + (size_t)r * 128 + c * 8);
        }
    }
    CP_COMMIT();
    // ---- group 1: Wb (waited only before phase 3) ------------------------
    for (int t = 0; t < 2; t++) {
        const bf16* src = ((t == 0) ? Wbh : Wbl) + (size_t)n * 192 * 64;
        for (int q = tid; q < 1536; q += 256) {
            int r = q >> 3, c = q & 7;
            int cp = c ^ (r & 7);
            cpa16(sb + FK_WB_OFF + t * 24576 + r * 128 + cp * 16,
                  src + (size_t)r * 64 + c * 8);
        }
    }
    CP_COMMIT();
    CP_WAIT1();
    __syncthreads();

    // ---- phase 1: contrib MMAs ------------------------------------------
    const int wm = (wid >> 2) * 64;
    const int wn128 = (wid & 3) * 32;
    const uint32_t a_base = (uint32_t)(wm + (lane & 15)) * 80 + ((lane >> 4) * 16);
    uint32_t b_off[2];
#pragma unroll
    for (int nt = 0; nt < 2; nt++) {
        int g  = (wn128 >> 3) + nt * 2 + (lane >> 4);
        int gp = (g & 8) | ((g ^ (lane & 7)) & 7);
        b_off[nt] = (uint32_t)(lane & 15) * 256 + gp * 16;
    }

    {
        float acc[4][4][4];
#pragma unroll
        for (int mt = 0; mt < 4; mt++)
#pragma unroll
            for (int j = 0; j < 4; j++)
#pragma unroll
                for (int r = 0; r < 4; r++) acc[mt][j][r] = 0.f;

#pragma unroll
        for (int cl = 0; cl < 6; cl++) {
            const uint32_t Apan = sb + FK_PX_OFF + (uint32_t)(((cl < 4) ? 0 : 2) + (cl & 1)) * FK_PANEL;
            const uint32_t Bk = sb + FK_WC_OFF + ((cl == 2 || cl == 3) ? 16384u : 0u)
                              + (uint32_t)((cl & 1) * 32) * 256;
#pragma unroll
            for (int kh = 0; kh < 2; kh++) {
                uint32_t a[4][4], b[2][4];
#pragma unroll
                for (int mt = 0; mt < 4; mt++)
                    LDSM_X4(a[mt][0], a[mt][1], a[mt][2], a[mt][3],
                            Apan + a_base + mt * (16 * 80) + kh * 32);
#pragma unroll
                for (int nt = 0; nt < 2; nt++)
                    LDSM_X4T(b[nt][0], b[nt][1], b[nt][2], b[nt][3],
                             Bk + b_off[nt] + kh * 4096);
#pragma unroll
                for (int mt = 0; mt < 4; mt++) {
                    MMA16816(acc[mt][0], a[mt], b[0][0], b[0][1]);
                    MMA16816(acc[mt][1], a[mt], b[0][2], b[0][3]);
                    MMA16816(acc[mt][2], a[mt], b[1][0], b[1][1]);
                    MMA16816(acc[mt][3], a[mt], b[1][2], b[1][3]);
                }
            }
        }

        const int er = lane >> 2, ec = (lane & 3) * 2;
#pragma unroll
        for (int mt = 0; mt < 4; mt++) {
#pragma unroll
            for (int jj = 0; jj < 4; jj++) {
                int row = wm + mt * 16 + er;
                int col = wn128 + jj * 8 + ec;
                uint32_t po = (uint32_t)(col >> 5) * FK_PANEL + (uint32_t)(col & 31) * 2;
                bf16 h0, l0, h1, l1;
                split1(acc[mt][jj][0], h0, l0); split1(acc[mt][jj][1], h1, l1);
                *(__nv_bfloat162*)(smem + FK_PH_OFF + po + row * 80) = __nv_bfloat162(h0, h1);
                *(__nv_bfloat162*)(smem + FK_PH_OFF + 4 * FK_PANEL + po + row * 80) = __nv_bfloat162(l0, l1);
                split1(acc[mt][jj][2], h0, l0); split1(acc[mt][jj][3], h1, l1);
                *(__nv_bfloat162*)(smem + FK_PH_OFF + po + (row + 8) * 80) = __nv_bfloat162(h0, h1);
                *(__nv_bfloat162*)(smem + FK_PH_OFF + 4 * FK_PANEL + po + (row + 8) * 80) = __nv_bfloat162(l0, l1);
            }
        }
    }
    __syncthreads();

    // ---- phase 2: 4-segment parallel scan (256 threads) ------------------
    {
        const int s = tid & 63;
        const int g = tid >> 6;                // segment 0..3, 32 chunks each
        const float a = Ar[n * 64 + s], w = Ai[n * 64 + s];
        const float p64 = expf(64.f * a);
        const float c64 = p64 * cosf(64.f * w), s64 = p64 * sinf(64.f * w);
        const int col = 2 * s;
        char* hbase = smem + FK_PH_OFF + (uint32_t)(col >> 5) * FK_PANEL + (uint32_t)(col & 31) * 2;
        char* lbase = hbase + 4 * FK_PANEL;
        float* se = (float*)(smem + FK_END_OFF);
        const int j0 = g * 32;

        float hr = 0.f, hi = 0.f;
#pragma unroll 8
        for (int jj = 0; jj < 32; jj++) {
            const int j = j0 + jj;
            __nv_bfloat162 chv = *(__nv_bfloat162*)(hbase + j * 80);
            __nv_bfloat162 clv = *(__nv_bfloat162*)(lbase + j * 80);
            float cr = __bfloat162float(chv.x) + __bfloat162float(clv.x);
            float ci = __bfloat162float(chv.y) + __bfloat162float(clv.y);
            bf16 h0, l0, h1, l1;
            split1(hr, h0, l0); split1(hi, h1, l1);
            *(__nv_bfloat162*)(hbase + j * 80) = __nv_bfloat162(h0, h1);
            *(__nv_bfloat162*)(lbase + j * 80) = __nv_bfloat162(l0, l1);
            float nr = c64 * hr - s64 * hi + cr;
            float ni = c64 * hi + s64 * hr + ci;
            hr = nr; hi = ni;
        }
        se[(g * 64 + s) * 2]     = hr;
        se[(g * 64 + s) * 2 + 1] = hi;
        __syncthreads();

        if (g > 0) {
            float pr = 0.f, pi = 0.f;
            for (int q = 0; q < g; q++) {
                float e = (float)(g - 1 - q);
                float pw = expf(2048.f * e * a);
                float cc = pw * cosf(2048.f * e * w), ss = pw * sinf(2048.f * e * w);
                float er_ = se[(q * 64 + s) * 2], ei_ = se[(q * 64 + s) * 2 + 1];
                pr += cc * er_ - ss * ei_;
                pi += cc * ei_ + ss * er_;
            }
            float vr = pr, vi = pi;
#pragma unroll 8
            for (int jj = 0; jj < 32; jj++) {
                const int j = j0 + jj;
                __nv_bfloat162 chv = *(__nv_bfloat162*)(hbase + j * 80);
                __nv_bfloat162 clv = *(__nv_bfloat162*)(lbase + j * 80);
                float sr = __bfloat162float(chv.x) + __bfloat162float(clv.x) + vr;
                float si = __bfloat162float(chv.y) + __bfloat162float(clv.y) + vi;
                bf16 h0, l0, h1, l1;
                split1(sr, h0, l0); split1(si, h1, l1);
                *(__nv_bfloat162*)(hbase + j * 80) = __nv_bfloat162(h0, h1);
                *(__nv_bfloat162*)(lbase + j * 80) = __nv_bfloat162(l0, l1);
                float nvr = c64 * vr - s64 * vi;
                float nvi = c64 * vi + s64 * vr;
                vr = nvr; vi = nvi;
            }
        }
    }
    CP_WAIT_ALL();
    __syncthreads();

    // ---- phase 3: conv MMAs ---------------------------------------------
    {
        const int wn = (wid & 3) * 16;
        float acc[4][2][4];
#pragma unroll
        for (int mt = 0; mt < 4; mt++)
#pragma unroll
            for (int j = 0; j < 2; j++)
#pragma unroll
                for (int r = 0; r < 4; r++) acc[mt][j][r] = 0.f;

#pragma unroll
        for (int cl = 0; cl < 18; cl++) {
            const int term = cl / 6, kc = cl % 6;
            uint32_t Apan;
            if (kc < 2)
                Apan = sb + FK_PX_OFF + (uint32_t)(((term < 2) ? 0 : 2) + kc) * FK_PANEL;
            else
                Apan = sb + FK_PH_OFF + (uint32_t)(((term < 2) ? 0 : 4) + (kc - 2)) * FK_PANEL;
            const uint32_t Bbase = sb + FK_WB_OFF + ((term == 1) ? 24576u : 0u)
                                 + (uint32_t)kc * 4096;
#pragma unroll
            for (int kh = 0; kh < 2; kh++) {
                uint32_t a[4][4], b[4];
#pragma unroll
                for (int mt = 0; mt < 4; mt++)
                    LDSM_X4(a[mt][0], a[mt][1], a[mt][2], a[mt][3],
                            Apan + a_base + mt * (16 * 80) + kh * 32);
                {
                    int krow = kh * 16 + (lane & 15);
                    int g = (wn >> 3) + (lane >> 4);
                    uint32_t boff = (uint32_t)krow * 128 + (uint32_t)(((g ^ (krow & 7)) & 7) * 16);
                    LDSM_X4T(b[0], b[1], b[2], b[3], Bbase + boff);
                }
#pragma unroll
                for (int mt = 0; mt < 4; mt++) {
                    MMA16816(acc[mt][0], a[mt], b[0], b[1]);
                    MMA16816(acc[mt][1], a[mt], b[2], b[3]);
                }
            }
        }

        const int er = lane >> 2, ec = (lane & 3) * 2;
        bf16* yhp = Yh + chain * L_DIM;
        bf16* ylp = Yl + chain * L_DIM;
#pragma unroll
        for (int mt = 0; mt < 4; mt++) {
#pragma unroll
            for (int j = 0; j < 2; j++) {
                int row0 = wm + mt * 16 + er;
                int tcol = wn + j * 8 + ec;
                size_t b0 = (size_t)row0 * 64 + tcol;
                bf16 h0, l0, h1, l1;
                split1(acc[mt][j][0], h0, l0); split1(acc[mt][j][1], h1, l1);
                *(__nv_bfloat162*)&yhp[b0] = __nv_bfloat162(h0, h1);
                *(__nv_bfloat162*)&ylp[b0] = __nv_bfloat162(l0, l1);
                size_t b1 = (size_t)(row0 + 8) * 64 + tcol;
                split1(acc[mt][j][2], h0, l0); split1(acc[mt][j][3], h1, l1);
                *(__nv_bfloat162*)&yhp[b1] = __nv_bfloat162(h0, h1);
                *(__nv_bfloat162*)&ylp[b1] = __nv_bfloat162(l0, l1);
            }
        }
    }
}

// ---------------------------------------------------------------------------
extern "C" void kernel_launch(void* const* d_in, const int* in_sizes, int n_in,
                              void* d_out, int out_size)
{
    const float* inp = (const float*)d_in[0];  // [B, C, L]
    const float* ar  = (const float*)d_in[1];  // [N, S]
    const float* ai  = (const float*)d_in[2];  // [N, S]
    const float* Bm  = (const float*)d_in[3];  // [N, C]
    const float* Cm  = (const float*)d_in[4];  // [C, N]
    const float* E   = (const float*)d_in[5];  // [N, S]
    float* out = (float*)d_out;                // [B, C, L]

    bf16 *inh, *inl, *xh, *xl, *yh, *yl, *bh, *bl, *ch, *cl;
    bf16 *wbh, *wbl, *wch, *wcl;
    cudaGetSymbolAddress((void**)&inh, g_inh);
    cudaGetSymbolAddress((void**)&inl, g_inl);
    cudaGetSymbolAddress((void**)&xh,  g_xh);
    cudaGetSymbolAddress((void**)&xl,  g_xl);
    cudaGetSymbolAddress((void**)&yh,  g_yh);
    cudaGetSymbolAddress((void**)&yl,  g_yl);
    cudaGetSymbolAddress((void**)&bh,  g_bh);
    cudaGetSymbolAddress((void**)&bl,  g_bl);
    cudaGetSymbolAddress((void**)&ch,  g_ch);
    cudaGetSymbolAddress((void**)&cl,  g_cl);
    cudaGetSymbolAddress((void**)&wbh, g_wbh);
    cudaGetSymbolAddress((void**)&wbl, g_wbl);
    cudaGetSymbolAddress((void**)&wch, g_wch);
    cudaGetSymbolAddress((void**)&wcl, g_wcl);

    cudaFuncSetAttribute(hgemm,        cudaFuncAttributeMaxDynamicSharedMemorySize, GEMM_SMEM);
    cudaFuncSetAttribute(prep_weights, cudaFuncAttributeMaxDynamicSharedMemorySize, PW_SMEM);
    cudaFuncSetAttribute(fused_mid,    cudaFuncAttributeMaxDynamicSharedMemorySize, FK_SMEM);

    split_all<<<SPLIT_GRID, 256>>>(inp, Bm, Cm, inh, inl, bh, bl, ch, cl);
    prep_weights<<<N_DIM, 256, PW_SMEM>>>(ar, ai, E, wbh, wbl, wch, wcl);

    dim3 gg(L_DIM / 128, N_DIM / 128, B_SZ);
    hgemm<<<gg, 256, GEMM_SMEM>>>(bh, bl, inh, inl, nullptr, xh, xl);     // x = B@input

    fused_mid<<<dim3(B_SZ, N_DIM), 256, FK_SMEM>>>(xh, xl, wch, wcl, wbh, wbl, ar, ai, yh, yl);

    hgemm<<<gg, 256, GEMM_SMEM>>>(ch, cl, yh, yl, out, nullptr, nullptr); // out = C@y
}

// round 15
// speedup vs baseline: 1.0014x; 1.0014x over previous
#include <cuda_runtime.h>
#include <cuda_bf16.h>
#include <cstdint>
#include <math.h>

#define B_SZ   4
#define C_DIM  512
#define N_DIM  512
#define S_DIM  64
#define L_DIM  8192
#define NCHK   128

typedef __nv_bfloat16 bf16;

// ---------------------------------------------------------------------------
// Scratch (allocation-free rule: __device__ globals)
// ---------------------------------------------------------------------------
__device__ __align__(128) bf16  g_inh[(size_t)B_SZ * C_DIM * L_DIM];
__device__ __align__(128) bf16  g_inl[(size_t)B_SZ * C_DIM * L_DIM];
__device__ __align__(128) bf16  g_xh [(size_t)B_SZ * N_DIM * L_DIM];
__device__ __align__(128) bf16  g_xl [(size_t)B_SZ * N_DIM * L_DIM];
__device__ __align__(128) bf16  g_yh [(size_t)B_SZ * N_DIM * L_DIM];
__device__ __align__(128) bf16  g_yl [(size_t)B_SZ * N_DIM * L_DIM];
__device__ __align__(128) bf16  g_bh [C_DIM * N_DIM];
__device__ __align__(128) bf16  g_bl [C_DIM * N_DIM];
__device__ __align__(128) bf16  g_ch [C_DIM * N_DIM];
__device__ __align__(128) bf16  g_cl [C_DIM * N_DIM];
__device__ __align__(128) bf16  g_wbh[(size_t)N_DIM * 192 * 64];
__device__ __align__(128) bf16  g_wbl[(size_t)N_DIM * 192 * 64];
__device__ __align__(128) bf16  g_wch[(size_t)N_DIM * 64 * 128];
__device__ __align__(128) bf16  g_wcl[(size_t)N_DIM * 64 * 128];

// ---------------------------------------------------------------------------
// Helpers (base PTX only)
// ---------------------------------------------------------------------------
__device__ __forceinline__ uint32_t smem_u32(const void* p) {
    uint32_t a;
    asm("{ .reg .u64 t; cvta.to.shared.u64 t, %1; cvt.u32.u64 %0, t; }" : "=r"(a) : "l"(p));
    return a;
}
__device__ __forceinline__ void cpa16(uint32_t d, const void* s) {
    asm volatile("cp.async.cg.shared.global [%0], [%1], 16;" :: "r"(d), "l"(s));
}
#define CP_COMMIT()   asm volatile("cp.async.commit_group;" ::: "memory")
#define CP_WAIT2()    asm volatile("cp.async.wait_group 2;"  ::: "memory")
#define CP_WAIT1()    asm volatile("cp.async.wait_group 1;"  ::: "memory")
#define CP_WAIT_ALL() asm volatile("cp.async.wait_group 0;" ::: "memory")

#define LDSM_X4(r0,r1,r2,r3,addr) \
    asm volatile("ldmatrix.sync.aligned.m8n8.x4.shared.b16 {%0,%1,%2,%3}, [%4];" \
        : "=r"(r0), "=r"(r1), "=r"(r2), "=r"(r3) : "r"(addr))
#define LDSM_X4T(r0,r1,r2,r3,addr) \
    asm volatile("ldmatrix.sync.aligned.m8n8.x4.trans.shared.b16 {%0,%1,%2,%3}, [%4];" \
        : "=r"(r0), "=r"(r1), "=r"(r2), "=r"(r3) : "r"(addr))

#define MMA16816(d, a, b0v, b1v) \
    asm volatile("mma.sync.aligned.m16n8k16.row.col.f32.bf16.bf16.f32 " \
        "{%0,%1,%2,%3}, {%4,%5,%6,%7}, {%8,%9}, {%0,%1,%2,%3};" \
        : "+f"((d)[0]), "+f"((d)[1]), "+f"((d)[2]), "+f"((d)[3]) \
        : "r"((a)[0]), "r"((a)[1]), "r"((a)[2]), "r"((a)[3]), "r"(b0v), "r"(b1v))

__device__ __forceinline__ void split1(float v, bf16& h, bf16& l) {
    h = __float2bfloat16_rn(v);
    l = __float2bfloat16_rn(v - __bfloat162float(h));
}

// ---------------------------------------------------------------------------
// Combined split pre-pass: one launch splits input, Bm, Cm.
// ---------------------------------------------------------------------------
#define SPLIT_IN_BLOCKS  (B_SZ * C_DIM * L_DIM / 1024)   // 16384
#define SPLIT_W_BLOCKS   (C_DIM * N_DIM / 1024)          // 256
#define SPLIT_GRID       (SPLIT_IN_BLOCKS + 2 * SPLIT_W_BLOCKS)

__global__ __launch_bounds__(256) void split_all(
    const float* __restrict__ inp, const float* __restrict__ Bm, const float* __restrict__ Cm,
    bf16* __restrict__ inh, bf16* __restrict__ inl,
    bf16* __restrict__ bh, bf16* __restrict__ bl,
    bf16* __restrict__ ch, bf16* __restrict__ cl)
{
    const int blk = blockIdx.x;
    const float* src;
    bf16 *hi, *lo;
    int base;
    if (blk < SPLIT_IN_BLOCKS) {
        src = inp; hi = inh; lo = inl; base = blk;
    } else if (blk < SPLIT_IN_BLOCKS + SPLIT_W_BLOCKS) {
        src = Bm;  hi = bh;  lo = bl;  base = blk - SPLIT_IN_BLOCKS;
    } else {
        src = Cm;  hi = ch;  lo = cl;  base = blk - SPLIT_IN_BLOCKS - SPLIT_W_BLOCKS;
    }
    int i = (base * 256 + threadIdx.x) * 4;
    float4 v = *(const float4*)(src + i);
    bf16 h0, l0, h1, l1, h2, l2, h3, l3;
    split1(v.x, h0, l0); split1(v.y, h1, l1);
    split1(v.z, h2, l2); split1(v.w, h3, l3);
    ((__nv_bfloat162*)(hi + i))[0] = __nv_bfloat162(h0, h1);
    ((__nv_bfloat162*)(hi + i))[1] = __nv_bfloat162(h2, h3);
    ((__nv_bfloat162*)(lo + i))[0] = __nv_bfloat162(l0, l1);
    ((__nv_bfloat162*)(lo + i))[1] = __nv_bfloat162(l2, l3);
}

// ---------------------------------------------------------------------------
// HMMA GEMM (proven 142us, R13 4-stage): Out[b] = W(512x512) @ X[b](512x8192)
// ---------------------------------------------------------------------------
#define STAGE   18432
#define A_BYTES 10240
#define NCHUNK  48
#define GEMM_SMEM (4 * STAGE)

__global__ __launch_bounds__(256, 2) void hgemm(
    const bf16* __restrict__ Ah, const bf16* __restrict__ Al,
    const bf16* __restrict__ Bh0, const bf16* __restrict__ Bl0,
    float* __restrict__ OutF, bf16* __restrict__ OutH, bf16* __restrict__ OutL)
{
    extern __shared__ char smem[];
    const uint32_t sb = smem_u32(smem);
    const int tid  = threadIdx.x;
    const int lane = tid & 31, wid = tid >> 5;
    const int n0 = blockIdx.x * 128;
    const int m0 = blockIdx.y * 128;
    const size_t boff = (size_t)blockIdx.z * C_DIM * L_DIM;
    const bf16* Bh = Bh0 + boff;
    const bf16* Bl = Bl0 + boff;

    const int am = tid >> 2, ac = tid & 3;
    const int bk = tid >> 4, bc = tid & 15;

    auto load_stage = [&](int cl, int st) {
        if (cl < NCHUNK) {
            const bf16* As = (cl < 32) ? Ah : Al;
            const bf16* Bs = (cl >= 16 && cl < 32) ? Bl : Bh;
            const int k0 = (cl & 15) << 5;
            const uint32_t s0 = sb + (uint32_t)st * STAGE;
            cpa16(s0 + am * 80 + ac * 16,
                  As + (size_t)(m0 + am) * C_DIM + k0 + ac * 8);
            cpa16(s0 + (am + 64) * 80 + ac * 16,
                  As + (size_t)(m0 + am + 64) * C_DIM + k0 + ac * 8);
            {
                int c1 = (bc & 8) | ((bc ^ (bk & 7)) & 7);
                cpa16(s0 + A_BYTES + bk * 256 + c1 * 16,
                      Bs + (size_t)(k0 + bk) * L_DIM + n0 + bc * 8);
                int k2 = bk + 16;
                int c2 = (bc & 8) | ((bc ^ (k2 & 7)) & 7);
                cpa16(s0 + A_BYTES + k2 * 256 + c2 * 16,
                      Bs + (size_t)(k0 + k2) * L_DIM + n0 + bc * 8);
            }
        }
        CP_COMMIT();
    };

    const int wm = (wid >> 2) * 64;
    const int wn = (wid & 3) * 32;
    const uint32_t a_base = (uint32_t)(wm + (lane & 15)) * 80 + ((lane >> 4) * 16);
    uint32_t b_off[2];
#pragma unroll
    for (int nt = 0; nt < 2; nt++) {
        int g  = (wn >> 3) + nt * 2 + (lane >> 4);
        int gp = (g & 8) | ((g ^ (lane & 7)) & 7);
        b_off[nt] = (uint32_t)(lane & 15) * 256 + gp * 16;
    }

    float acc[4][4][4];
#pragma unroll
    for (int mt = 0; mt < 4; mt++)
#pragma unroll
        for (int j = 0; j < 4; j++)
#pragma unroll
            for (int r = 0; r < 4; r++) acc[mt][j][r] = 0.f;

    load_stage(0, 0); load_stage(1, 1); load_stage(2, 2);

    for (int c = 0; c < NCHUNK; c++) {
        CP_WAIT2();
        __syncthreads();
        load_stage(c + 3, (c + 3) & 3);

        const uint32_t Abase = sb + (uint32_t)(c & 3) * STAGE;
        const uint32_t Bbase = Abase + A_BYTES;
#pragma unroll
        for (int kh = 0; kh < 2; kh++) {
            uint32_t a[4][4], b[2][4];
#pragma unroll
            for (int mt = 0; mt < 4; mt++)
                LDSM_X4(a[mt][0], a[mt][1], a[mt][2], a[mt][3],
                        Abase + a_base + mt * (16 * 80) + kh * 32);
#pragma unroll
            for (int nt = 0; nt < 2; nt++)
                LDSM_X4T(b[nt][0], b[nt][1], b[nt][2], b[nt][3],
                         Bbase + b_off[nt] + kh * 4096);
#pragma unroll
            for (int mt = 0; mt < 4; mt++) {
                MMA16816(acc[mt][0], a[mt], b[0][0], b[0][1]);
                MMA16816(acc[mt][1], a[mt], b[0][2], b[0][3]);
                MMA16816(acc[mt][2], a[mt], b[1][0], b[1][1]);
                MMA16816(acc[mt][3], a[mt], b[1][2], b[1][3]);
            }
        }
    }

    const int er = lane >> 2, ec = (lane & 3) * 2;
    const size_t outz = (size_t)blockIdx.z * N_DIM * L_DIM;
#pragma unroll
    for (int mt = 0; mt < 4; mt++) {
#pragma unroll
        for (int j = 0; j < 4; j++) {
            size_t base = outz + (size_t)(m0 + wm + mt * 16 + er) * L_DIM + (n0 + wn + j * 8 + ec);
            if (OutF) {
                *(float2*)&OutF[base]             = make_float2(acc[mt][j][0], acc[mt][j][1]);
                *(float2*)&OutF[base + 8 * L_DIM] = make_float2(acc[mt][j][2], acc[mt][j][3]);
            } else {
                bf16 h0, l0, h1, l1;
                split1(acc[mt][j][0], h0, l0); split1(acc[mt][j][1], h1, l1);
                *(__nv_bfloat162*)&OutH[base] = __nv_bfloat162(h0, h1);
                *(__nv_bfloat162*)&OutL[base] = __nv_bfloat162(l0, l1);
                split1(acc[mt][j][2], h0, l0); split1(acc[mt][j][3], h1, l1);
                *(__nv_bfloat162*)&OutH[base + 8 * L_DIM] = __nv_bfloat162(h0, h1);
                *(__nv_bfloat162*)&OutL[base + 8 * L_DIM] = __nv_bfloat162(l0, l1);
            }
        }
    }
}

// ---------------------------------------------------------------------------
// Prep (parallel, closed-form) — proven 20us
// ---------------------------------------------------------------------------
#define PW_WB_OFF 0
#define PW_WC_OFF (192 * 65)
#define PW_P_OFF  (PW_WC_OFF + 64 * 128)
#define PW_K_OFF  (PW_P_OFF + 64 * 65)
#define PW_SMEM   ((PW_K_OFF + 64) * 4)

__global__ __launch_bounds__(256) void prep_weights(
    const float* __restrict__ Ar, const float* __restrict__ Ai,
    const float* __restrict__ Ew,
    bf16* __restrict__ wbh, bf16* __restrict__ wbl,
    bf16* __restrict__ wch, bf16* __restrict__ wcl)
{
    extern __shared__ float sm[];
    float* sWb = sm + PW_WB_OFF;
    float* sWc = sm + PW_WC_OFF;
    float* sP  = sm + PW_P_OFF;
    float* sK  = sm + PW_K_OFF;

    const int n = blockIdx.x;
    const int tid = threadIdx.x;
    const int s = tid & 63;
    const int dg = tid >> 6;

    const float a = Ar[n * 64 + s], w = Ai[n * 64 + s], E = Ew[n * 64 + s];
    const float er = expf(a);
    const float lr = er * cosf(w), li = er * sinf(w);

#pragma unroll
    for (int dd = 0; dd < 16; dd++) {
        const int d = dg * 16 + dd;
        const float fd = (float)d;
        const float p  = expf(fd * a);
        const float cr = p * cosf(fd * w);
        const float ci = p * sinf(fd * w);
        sWc[(63 - d) * 128 + 2 * s]     = cr;
        sWc[(63 - d) * 128 + 2 * s + 1] = ci;
        sP[d * 65 + s] = E * cr;
        const float cr1 = cr * lr - ci * li;
        const float ci1 = cr * li + ci * lr;
        sWb[(64 + 2 * s) * 65 + d] = E * cr1;
        sWb[(65 + 2 * s) * 65 + d] = -E * ci1;
    }
    __syncthreads();
    if (tid < 64) {
        float acc = 0.f;
#pragma unroll
        for (int q = 0; q < 64; q++) acc += sP[tid * 65 + q];
        sK[tid] = acc;
    }
    __syncthreads();
    for (int i = tid; i < 64 * 64; i += 256) {
        int k = i >> 6, t = i & 63;
        sWb[k * 65 + t] = (t >= k) ? sK[t - k] : 0.f;
    }
    __syncthreads();
    {
        bf16* dh = wbh + (size_t)n * 192 * 64;
        bf16* dl = wbl + (size_t)n * 192 * 64;
        for (int i = tid; i < 192 * 64; i += 256) {
            int r = i >> 6, t = i & 63;
            bf16 h, l; split1(sWb[r * 65 + t], h, l);
            dh[i] = h; dl[i] = l;
        }
    }
    {
        bf16* dh = wch + (size_t)n * 64 * 128;
        bf16* dl = wcl + (size_t)n * 64 * 128;
        for (int i = tid; i < 64 * 128; i += 256) {
            bf16 h, l; split1(sWc[i], h, l);
            dh[i] = h; dl[i] = l;
        }
    }
}

// ---------------------------------------------------------------------------
// FUSED middle kernel (R13 exact): 256 threads, 4-segment parallel scan,
// Wb load overlapped behind phase 1 + scan.
// ---------------------------------------------------------------------------
#define FK_PANEL   10320
#define FK_PX_OFF  0
#define FK_PH_OFF  (4 * FK_PANEL)
#define FK_WC_OFF  (12 * FK_PANEL)
#define FK_WB_OFF  (FK_WC_OFF + 32768)
#define FK_END_OFF (FK_WB_OFF + 49152)
#define FK_SMEM    (FK_END_OFF + 2048)

__global__ __launch_bounds__(256, 1) void fused_mid(
    const bf16* __restrict__ Xh, const bf16* __restrict__ Xl,
    const bf16* __restrict__ Wch, const bf16* __restrict__ Wcl,
    const bf16* __restrict__ Wbh, const bf16* __restrict__ Wbl,
    const float* __restrict__ Ar, const float* __restrict__ Ai,
    bf16* __restrict__ Yh, bf16* __restrict__ Yl)
{
    extern __shared__ char smem[];
    const uint32_t sb = smem_u32(smem);
    const int tid  = threadIdx.x;
    const int lane = tid & 31, wid = tid >> 5;
    const int bb = blockIdx.x;
    const int n  = blockIdx.y;
    const size_t chain = (size_t)bb * N_DIM + n;

    // ---- group 0: x + Wc ------------------------------------------------
    for (int t = 0; t < 2; t++) {
        const bf16* src = (t == 0) ? (Xh + chain * L_DIM) : (Xl + chain * L_DIM);
        for (int q = tid; q < 1024; q += 256) {
            int j = q >> 3, c = q & 7;
            uint32_t dst = sb + FK_PX_OFF + (uint32_t)(t * 2 + (c >> 2)) * FK_PANEL
                         + j * 80 + (c & 3) * 16;
            cpa16(dst, src + (size_t)j * 64 + c * 8);
        }
    }
    for (int t = 0; t < 2; t++) {
        const bf16* src = ((t == 0) ? Wch : Wcl) + (size_t)n * 64 * 128;
        for (int q = tid; q < 1024; q += 256) {
            int r = q >> 4, c = q & 15;
            int cp = (c & 8) | ((c ^ (r & 7)) & 7);
            cpa16(sb + FK_WC_OFF + t * 16384 + r * 256 + cp * 16,
                  src + (size_t)r * 128 + c * 8);
        }
    }
    CP_COMMIT();
    // ---- group 1: Wb (waited only before phase 3) ------------------------
    for (int t = 0; t < 2; t++) {
        const bf16* src = ((t == 0) ? Wbh : Wbl) + (size_t)n * 192 * 64;
        for (int q = tid; q < 1536; q += 256) {
            int r = q >> 3, c = q & 7;
            int cp = c ^ (r & 7);
            cpa16(sb + FK_WB_OFF + t * 24576 + r * 128 + cp * 16,
                  src + (size_t)r * 64 + c * 8);
        }
    }
    CP_COMMIT();
    CP_WAIT1();
    __syncthreads();

    // ---- phase 1: contrib MMAs ------------------------------------------
    const int wm = (wid >> 2) * 64;
    const int wn128 = (wid & 3) * 32;
    const uint32_t a_base = (uint32_t)(wm + (lane & 15)) * 80 + ((lane >> 4) * 16);
    uint32_t b_off[2];
#pragma unroll
    for (int nt = 0; nt < 2; nt++) {
        int g  = (wn128 >> 3) + nt * 2 + (lane >> 4);
        int gp = (g & 8) | ((g ^ (lane & 7)) & 7);
        b_off[nt] = (uint32_t)(lane & 15) * 256 + gp * 16;
    }

    {
        float acc[4][4][4];
#pragma unroll
        for (int mt = 0; mt < 4; mt++)
#pragma unroll
            for (int j = 0; j < 4; j++)
#pragma unroll
                for (int r = 0; r < 4; r++) acc[mt][j][r] = 0.f;

#pragma unroll
        for (int cl = 0; cl < 6; cl++) {
            const uint32_t Apan = sb + FK_PX_OFF + (uint32_t)(((cl < 4) ? 0 : 2) + (cl & 1)) * FK_PANEL;
            const uint32_t Bk = sb + FK_WC_OFF + ((cl == 2 || cl == 3) ? 16384u : 0u)
                              + (uint32_t)((cl & 1) * 32) * 256;
#pragma unroll
            for (int kh = 0; kh < 2; kh++) {
                uint32_t a[4][4], b[2][4];
#pragma unroll
                for (int mt = 0; mt < 4; mt++)
                    LDSM_X4(a[mt][0], a[mt][1], a[mt][2], a[mt][3],
                            Apan + a_base + mt * (16 * 80) + kh * 32);
#pragma unroll
                for (int nt = 0; nt < 2; nt++)
                    LDSM_X4T(b[nt][0], b[nt][1], b[nt][2], b[nt][3],
                             Bk + b_off[nt] + kh * 4096);
#pragma unroll
                for (int mt = 0; mt < 4; mt++) {
                    MMA16816(acc[mt][0], a[mt], b[0][0], b[0][1]);
                    MMA16816(acc[mt][1], a[mt], b[0][2], b[0][3]);
                    MMA16816(acc[mt][2], a[mt], b[1][0], b[1][1]);
                    MMA16816(acc[mt][3], a[mt], b[1][2], b[1][3]);
                }
            }
        }

        const int er = lane >> 2, ec = (lane & 3) * 2;
#pragma unroll
        for (int mt = 0; mt < 4; mt++) {
#pragma unroll
            for (int jj = 0; jj < 4; jj++) {
                int row = wm + mt * 16 + er;
                int col = wn128 + jj * 8 + ec;
                uint32_t po = (uint32_t)(col >> 5) * FK_PANEL + (uint32_t)(col & 31) * 2;
                bf16 h0, l0, h1, l1;
                split1(acc[mt][jj][0], h0, l0); split1(acc[mt][jj][1], h1, l1);
                *(__nv_bfloat162*)(smem + FK_PH_OFF + po + row * 80) = __nv_bfloat162(h0, h1);
                *(__nv_bfloat162*)(smem + FK_PH_OFF + 4 * FK_PANEL + po + row * 80) = __nv_bfloat162(l0, l1);
                split1(acc[mt][jj][2], h0, l0); split1(acc[mt][jj][3], h1, l1);
                *(__nv_bfloat162*)(smem + FK_PH_OFF + po + (row + 8) * 80) = __nv_bfloat162(h0, h1);
                *(__nv_bfloat162*)(smem + FK_PH_OFF + 4 * FK_PANEL + po + (row + 8) * 80) = __nv_bfloat162(l0, l1);
            }
        }
    }
    __syncthreads();

    // ---- phase 2: 4-segment parallel scan (256 threads) ------------------
    {
        const int s = tid & 63;
        const int g = tid >> 6;                // segment 0..3, 32 chunks each
        const float a = Ar[n * 64 + s], w = Ai[n * 64 + s];
        const float p64 = expf(64.f * a);
        const float c64 = p64 * cosf(64.f * w), s64 = p64 * sinf(64.f * w);
        const int col = 2 * s;
        char* hbase = smem + FK_PH_OFF + (uint32_t)(col >> 5) * FK_PANEL + (uint32_t)(col & 31) * 2;
        char* lbase = hbase + 4 * FK_PANEL;
        float* se = (float*)(smem + FK_END_OFF);
        const int j0 = g * 32;

        float hr = 0.f, hi = 0.f;
#pragma unroll 8
        for (int jj = 0; jj < 32; jj++) {
            const int j = j0 + jj;
            __nv_bfloat162 chv = *(__nv_bfloat162*)(hbase + j * 80);
            __nv_bfloat162 clv = *(__nv_bfloat162*)(lbase + j * 80);
            float cr = __bfloat162float(chv.x) + __bfloat162float(clv.x);
            float ci = __bfloat162float(chv.y) + __bfloat162float(clv.y);
            bf16 h0, l0, h1, l1;
            split1(hr, h0, l0); split1(hi, h1, l1);
            *(__nv_bfloat162*)(hbase + j * 80) = __nv_bfloat162(h0, h1);
            *(__nv_bfloat162*)(lbase + j * 80) = __nv_bfloat162(l0, l1);
            float nr = c64 * hr - s64 * hi + cr;
            float ni = c64 * hi + s64 * hr + ci;
            hr = nr; hi = ni;
        }
        se[(g * 64 + s) * 2]     = hr;
        se[(g * 64 + s) * 2 + 1] = hi;
        __syncthreads();

        if (g > 0) {
            float pr = 0.f, pi = 0.f;
            for (int q = 0; q < g; q++) {
                float e = (float)(g - 1 - q);
                float pw = expf(2048.f * e * a);
                float cc = pw * cosf(2048.f * e * w), ss = pw * sinf(2048.f * e * w);
                float er_ = se[(q * 64 + s) * 2], ei_ = se[(q * 64 + s) * 2 + 1];
                pr += cc * er_ - ss * ei_;
                pi += cc * ei_ + ss * er_;
            }
            float vr = pr, vi = pi;
#pragma unroll 8
            for (int jj = 0; jj < 32; jj++) {
                const int j = j0 + jj;
                __nv_bfloat162 chv = *(__nv_bfloat162*)(hbase + j * 80);
                __nv_bfloat162 clv = *(__nv_bfloat162*)(lbase + j * 80);
                float sr = __bfloat162float(chv.x) + __bfloat162float(clv.x) + vr;
                float si = __bfloat162float(chv.y) + __bfloat162float(clv.y) + vi;
                bf16 h0, l0, h1, l1;
                split1(sr, h0, l0); split1(si, h1, l1);
                *(__nv_bfloat162*)(hbase + j * 80) = __nv_bfloat162(h0, h1);
                *(__nv_bfloat162*)(lbase + j * 80) = __nv_bfloat162(l0, l1);
                float nvr = c64 * vr - s64 * vi;
                float nvi = c64 * vi + s64 * vr;
                vr = nvr; vi = nvi;
            }
        }
    }
    CP_WAIT_ALL();
    __syncthreads();

    // ---- phase 3: conv MMAs ---------------------------------------------
    {
        const int wn = (wid & 3) * 16;
        float acc[4][2][4];
#pragma unroll
        for (int mt = 0; mt < 4; mt++)
#pragma unroll
            for (int j = 0; j < 2; j++)
#pragma unroll
                for (int r = 0; r < 4; r++) acc[mt][j][r] = 0.f;

#pragma unroll
        for (int cl = 0; cl < 18; cl++) {
            const int term = cl / 6, kc = cl % 6;
            uint32_t Apan;
            if (kc < 2)
                Apan = sb + FK_PX_OFF + (uint32_t)(((term < 2) ? 0 : 2) + kc) * FK_PANEL;
            else
                Apan = sb + FK_PH_OFF + (uint32_t)(((term < 2) ? 0 : 4) + (kc - 2)) * FK_PANEL;
            const uint32_t Bbase = sb + FK_WB_OFF + ((term == 1) ? 24576u : 0u)
                                 + (uint32_t)kc * 4096;
#pragma unroll
            for (int kh = 0; kh < 2; kh++) {
                uint32_t a[4][4], b[4];
#pragma unroll
                for (int mt = 0; mt < 4; mt++)
                    LDSM_X4(a[mt][0], a[mt][1], a[mt][2], a[mt][3],
                            Apan + a_base + mt * (16 * 80) + kh * 32);
                {
                    int krow = kh * 16 + (lane & 15);
                    int g = (wn >> 3) + (lane >> 4);
                    uint32_t boff = (uint32_t)krow * 128 + (uint32_t)(((g ^ (krow & 7)) & 7) * 16);
                    LDSM_X4T(b[0], b[1], b[2], b[3], Bbase + boff);
                }
#pragma unroll
                for (int mt = 0; mt < 4; mt++) {
                    MMA16816(acc[mt][0], a[mt], b[0], b[1]);
                    MMA16816(acc[mt][1], a[mt], b[2], b[3]);
                }
            }
        }

        const int er = lane >> 2, ec = (lane & 3) * 2;
        bf16* yhp = Yh + chain * L_DIM;
        bf16* ylp = Yl + chain * L_DIM;
#pragma unroll
        for (int mt = 0; mt < 4; mt++) {
#pragma unroll
            for (int j = 0; j < 2; j++) {
                int row0 = wm + mt * 16 + er;
                int tcol = wn + j * 8 + ec;
                size_t b0 = (size_t)row0 * 64 + tcol;
                bf16 h0, l0, h1, l1;
                split1(acc[mt][j][0], h0, l0); split1(acc[mt][j][1], h1, l1);
                *(__nv_bfloat162*)&yhp[b0] = __nv_bfloat162(h0, h1);
                *(__nv_bfloat162*)&ylp[b0] = __nv_bfloat162(l0, l1);
                size_t b1 = (size_t)(row0 + 8) * 64 + tcol;
                split1(acc[mt][j][2], h0, l0); split1(acc[mt][j][3], h1, l1);
                *(__nv_bfloat162*)&yhp[b1] = __nv_bfloat162(h0, h1);
                *(__nv_bfloat162*)&ylp[b1] = __nv_bfloat162(l0, l1);
            }
        }
    }
}

// ---------------------------------------------------------------------------
extern "C" void kernel_launch(void* const* d_in, const int* in_sizes, int n_in,
                              void* d_out, int out_size)
{
    const float* inp = (const float*)d_in[0];  // [B, C, L]
    const float* ar  = (const float*)d_in[1];  // [N, S]
    const float* ai  = (const float*)d_in[2];  // [N, S]
    const float* Bm  = (const float*)d_in[3];  // [N, C]
    const float* Cm  = (const float*)d_in[4];  // [C, N]
    const float* E   = (const float*)d_in[5];  // [N, S]
    float* out = (float*)d_out;                // [B, C, L]

    bf16 *inh, *inl, *xh, *xl, *yh, *yl, *bh, *bl, *ch, *cl;
    bf16 *wbh, *wbl, *wch, *wcl;
    cudaGetSymbolAddress((void**)&inh, g_inh);
    cudaGetSymbolAddress((void**)&inl, g_inl);
    cudaGetSymbolAddress((void**)&xh,  g_xh);
    cudaGetSymbolAddress((void**)&xl,  g_xl);
    cudaGetSymbolAddress((void**)&yh,  g_yh);
    cudaGetSymbolAddress((void**)&yl,  g_yl);
    cudaGetSymbolAddress((void**)&bh,  g_bh);
    cudaGetSymbolAddress((void**)&bl,  g_bl);
    cudaGetSymbolAddress((void**)&ch,  g_ch);
    cudaGetSymbolAddress((void**)&cl,  g_cl);
    cudaGetSymbolAddress((void**)&wbh, g_wbh);
    cudaGetSymbolAddress((void**)&wbl, g_wbl);
    cudaGetSymbolAddress((void**)&wch, g_wch);
    cudaGetSymbolAddress((void**)&wcl, g_wcl);

    cudaFuncSetAttribute(hgemm,        cudaFuncAttributeMaxDynamicSharedMemorySize, GEMM_SMEM);
    cudaFuncSetAttribute(prep_weights, cudaFuncAttributeMaxDynamicSharedMemorySize, PW_SMEM);
    cudaFuncSetAttribute(fused_mid,    cudaFuncAttributeMaxDynamicSharedMemorySize, FK_SMEM);

    // Fork/join two-stream schedule (capture-safe pattern):
    //   s1: split_all -> hgemm1 -> [wait prep] fused_mid -> hgemm2
    //   s2: prep_weights          (hidden behind split_all + hgemm1)
    // Streams/events are host-side capture mechanics: created and destroyed
    // every call (no statics, no device allocations); zero cost at replay.
    cudaStream_t s1, s2;
    cudaStreamCreate(&s1);
    cudaStreamCreate(&s2);
    cudaEvent_t evA, evP, evB;
    cudaEventCreateWithFlags(&evA, cudaEventDisableTiming);
    cudaEventCreateWithFlags(&evP, cudaEventDisableTiming);
    cudaEventCreateWithFlags(&evB, cudaEventDisableTiming);

    cudaEventRecord(evA, 0);            // fork from capture-origin (null) stream
    cudaStreamWaitEvent(s1, evA, 0);
    cudaStreamWaitEvent(s2, evA, 0);

    prep_weights<<<N_DIM, 256, PW_SMEM, s2>>>(ar, ai, E, wbh, wbl, wch, wcl);
    cudaEventRecord(evP, s2);

    split_all<<<SPLIT_GRID, 256, 0, s1>>>(inp, Bm, Cm, inh, inl, bh, bl, ch, cl);

    dim3 gg(L_DIM / 128, N_DIM / 128, B_SZ);
    hgemm<<<gg, 256, GEMM_SMEM, s1>>>(bh, bl, inh, inl, nullptr, xh, xl);   // x = B@input

    cudaStreamWaitEvent(s1, evP, 0);    // fused_mid needs prep's weights
    fused_mid<<<dim3(B_SZ, N_DIM), 256, FK_SMEM, s1>>>(xh, xl, wch, wcl, wbh, wbl, ar, ai, yh, yl);

    hgemm<<<gg, 256, GEMM_SMEM, s1>>>(ch, cl, yh, yl, out, nullptr, nullptr); // out = C@y

    cudaEventRecord(evB, s1);
    cudaStreamWaitEvent(0, evB, 0);     // join back to capture-origin stream

    cudaEventDestroy(evA);
    cudaEventDestroy(evP);
    cudaEventDestroy(evB);
    cudaStreamDestroy(s1);
    cudaStreamDestroy(s2);
}

// round 16
// speedup vs baseline: 1.2938x; 1.2921x over previous
#include <cuda_runtime.h>
#include <cuda_bf16.h>
#include <cuda_fp16.h>
#include <cstdint>
#include <math.h>

#define B_SZ   4
#define C_DIM  512
#define N_DIM  512
#define S_DIM  64
#define L_DIM  8192
#define NCHK   128

typedef __nv_bfloat16 bf16;

// ---------------------------------------------------------------------------
// Scratch (allocation-free rule: __device__ globals)
// ---------------------------------------------------------------------------
__device__ __align__(128) bf16   g_inh[(size_t)B_SZ * C_DIM * L_DIM];
__device__ __align__(128) bf16   g_inl[(size_t)B_SZ * C_DIM * L_DIM];
__device__ __align__(128) __half g_x16[(size_t)B_SZ * N_DIM * L_DIM];   // gemm1 out (fp16 single)
__device__ __align__(128) bf16   g_yh [(size_t)B_SZ * N_DIM * L_DIM];
__device__ __align__(128) bf16   g_yl [(size_t)B_SZ * N_DIM * L_DIM];
__device__ __align__(128) bf16   g_bh [C_DIM * N_DIM];
__device__ __align__(128) bf16   g_bl [C_DIM * N_DIM];
__device__ __align__(128) bf16   g_ch [C_DIM * N_DIM];
__device__ __align__(128) bf16   g_cl [C_DIM * N_DIM];
__device__ __align__(128) __half g_wb16[(size_t)N_DIM * 192 * 64];
__device__ __align__(128) __half g_wc16[(size_t)N_DIM * 64 * 128];

// ---------------------------------------------------------------------------
// Helpers (base PTX only)
// ---------------------------------------------------------------------------
__device__ __forceinline__ uint32_t smem_u32(const void* p) {
    uint32_t a;
    asm("{ .reg .u64 t; cvta.to.shared.u64 t, %1; cvt.u32.u64 %0, t; }" : "=r"(a) : "l"(p));
    return a;
}
__device__ __forceinline__ void cpa16(uint32_t d, const void* s) {
    asm volatile("cp.async.cg.shared.global [%0], [%1], 16;" :: "r"(d), "l"(s));
}
#define CP_COMMIT()   asm volatile("cp.async.commit_group;" ::: "memory")
#define CP_WAIT2()    asm volatile("cp.async.wait_group 2;"  ::: "memory")
#define CP_WAIT1()    asm volatile("cp.async.wait_group 1;"  ::: "memory")
#define CP_WAIT_ALL() asm volatile("cp.async.wait_group 0;" ::: "memory")

#define LDSM_X4(r0,r1,r2,r3,addr) \
    asm volatile("ldmatrix.sync.aligned.m8n8.x4.shared.b16 {%0,%1,%2,%3}, [%4];" \
        : "=r"(r0), "=r"(r1), "=r"(r2), "=r"(r3) : "r"(addr))
#define LDSM_X4T(r0,r1,r2,r3,addr) \
    asm volatile("ldmatrix.sync.aligned.m8n8.x4.trans.shared.b16 {%0,%1,%2,%3}, [%4];" \
        : "=r"(r0), "=r"(r1), "=r"(r2), "=r"(r3) : "r"(addr))

#define MMA16816(d, a, b0v, b1v) \
    asm volatile("mma.sync.aligned.m16n8k16.row.col.f32.bf16.bf16.f32 " \
        "{%0,%1,%2,%3}, {%4,%5,%6,%7}, {%8,%9}, {%0,%1,%2,%3};" \
        : "+f"((d)[0]), "+f"((d)[1]), "+f"((d)[2]), "+f"((d)[3]) \
        : "r"((a)[0]), "r"((a)[1]), "r"((a)[2]), "r"((a)[3]), "r"(b0v), "r"(b1v))

#define MMA16816H(d, a, b0v, b1v) \
    asm volatile("mma.sync.aligned.m16n8k16.row.col.f32.f16.f16.f32 " \
        "{%0,%1,%2,%3}, {%4,%5,%6,%7}, {%8,%9}, {%0,%1,%2,%3};" \
        : "+f"((d)[0]), "+f"((d)[1]), "+f"((d)[2]), "+f"((d)[3]) \
        : "r"((a)[0]), "r"((a)[1]), "r"((a)[2]), "r"((a)[3]), "r"(b0v), "r"(b1v))

__device__ __forceinline__ void split1(float v, bf16& h, bf16& l) {
    h = __float2bfloat16_rn(v);
    l = __float2bfloat16_rn(v - __bfloat162float(h));
}

// ---------------------------------------------------------------------------
// Combined split pre-pass (input + Bm + Cm), proven R13.
// ---------------------------------------------------------------------------
#define SPLIT_IN_BLOCKS  (B_SZ * C_DIM * L_DIM / 1024)   // 16384
#define SPLIT_W_BLOCKS   (C_DIM * N_DIM / 1024)          // 256
#define SPLIT_GRID       (SPLIT_IN_BLOCKS + 2 * SPLIT_W_BLOCKS)

__global__ __launch_bounds__(256) void split_all(
    const float* __restrict__ inp, const float* __restrict__ Bm, const float* __restrict__ Cm,
    bf16* __restrict__ inh, bf16* __restrict__ inl,
    bf16* __restrict__ bh, bf16* __restrict__ bl,
    bf16* __restrict__ ch, bf16* __restrict__ cl)
{
    const int blk = blockIdx.x;
    const float* src;
    bf16 *hi, *lo;
    int base;
    if (blk < SPLIT_IN_BLOCKS) {
        src = inp; hi = inh; lo = inl; base = blk;
    } else if (blk < SPLIT_IN_BLOCKS + SPLIT_W_BLOCKS) {
        src = Bm;  hi = bh;  lo = bl;  base = blk - SPLIT_IN_BLOCKS;
    } else {
        src = Cm;  hi = ch;  lo = cl;  base = blk - SPLIT_IN_BLOCKS - SPLIT_W_BLOCKS;
    }
    int i = (base * 256 + threadIdx.x) * 4;
    float4 v = *(const float4*)(src + i);
    bf16 h0, l0, h1, l1, h2, l2, h3, l3;
    split1(v.x, h0, l0); split1(v.y, h1, l1);
    split1(v.z, h2, l2); split1(v.w, h3, l3);
    ((__nv_bfloat162*)(hi + i))[0] = __nv_bfloat162(h0, h1);
    ((__nv_bfloat162*)(hi + i))[1] = __nv_bfloat162(h2, h3);
    ((__nv_bfloat162*)(lo + i))[0] = __nv_bfloat162(l0, l1);
    ((__nv_bfloat162*)(lo + i))[1] = __nv_bfloat162(l2, l3);
}

// ---------------------------------------------------------------------------
// HMMA GEMM (proven): Out[b] = W(512x512) @ X[b](512x8192)
// Output modes: OutF fp32 | (OutH,OutL) bf16 split | Out16 fp16 single.
// ---------------------------------------------------------------------------
#define STAGE   18432
#define A_BYTES 10240
#define NCHUNK  48
#define GEMM_SMEM (4 * STAGE)

__global__ __launch_bounds__(256, 2) void hgemm(
    const bf16* __restrict__ Ah, const bf16* __restrict__ Al,
    const bf16* __restrict__ Bh0, const bf16* __restrict__ Bl0,
    float* __restrict__ OutF, bf16* __restrict__ OutH, bf16* __restrict__ OutL,
    __half* __restrict__ Out16)
{
    extern __shared__ char smem[];
    const uint32_t sb = smem_u32(smem);
    const int tid  = threadIdx.x;
    const int lane = tid & 31, wid = tid >> 5;
    const int n0 = blockIdx.x * 128;
    const int m0 = blockIdx.y * 128;
    const size_t boff = (size_t)blockIdx.z * C_DIM * L_DIM;
    const bf16* Bh = Bh0 + boff;
    const bf16* Bl = Bl0 + boff;

    const int am = tid >> 2, ac = tid & 3;
    const int bk = tid >> 4, bc = tid & 15;

    auto load_stage = [&](int cl, int st) {
        if (cl < NCHUNK) {
            const bf16* As = (cl < 32) ? Ah : Al;
            const bf16* Bs = (cl >= 16 && cl < 32) ? Bl : Bh;
            const int k0 = (cl & 15) << 5;
            const uint32_t s0 = sb + (uint32_t)st * STAGE;
            cpa16(s0 + am * 80 + ac * 16,
                  As + (size_t)(m0 + am) * C_DIM + k0 + ac * 8);
            cpa16(s0 + (am + 64) * 80 + ac * 16,
                  As + (size_t)(m0 + am + 64) * C_DIM + k0 + ac * 8);
            {
                int c1 = (bc & 8) | ((bc ^ (bk & 7)) & 7);
                cpa16(s0 + A_BYTES + bk * 256 + c1 * 16,
                      Bs + (size_t)(k0 + bk) * L_DIM + n0 + bc * 8);
                int k2 = bk + 16;
                int c2 = (bc & 8) | ((bc ^ (k2 & 7)) & 7);
                cpa16(s0 + A_BYTES + k2 * 256 + c2 * 16,
                      Bs + (size_t)(k0 + k2) * L_DIM + n0 + bc * 8);
            }
        }
        CP_COMMIT();
    };

    const int wm = (wid >> 2) * 64;
    const int wn = (wid & 3) * 32;
    const uint32_t a_base = (uint32_t)(wm + (lane & 15)) * 80 + ((lane >> 4) * 16);
    uint32_t b_off[2];
#pragma unroll
    for (int nt = 0; nt < 2; nt++) {
        int g  = (wn >> 3) + nt * 2 + (lane >> 4);
        int gp = (g & 8) | ((g ^ (lane & 7)) & 7);
        b_off[nt] = (uint32_t)(lane & 15) * 256 + gp * 16;
    }

    float acc[4][4][4];
#pragma unroll
    for (int mt = 0; mt < 4; mt++)
#pragma unroll
        for (int j = 0; j < 4; j++)
#pragma unroll
            for (int r = 0; r < 4; r++) acc[mt][j][r] = 0.f;

    load_stage(0, 0); load_stage(1, 1); load_stage(2, 2);

    for (int c = 0; c < NCHUNK; c++) {
        CP_WAIT2();
        __syncthreads();
        load_stage(c + 3, (c + 3) & 3);

        const uint32_t Abase = sb + (uint32_t)(c & 3) * STAGE;
        const uint32_t Bbase = Abase + A_BYTES;
#pragma unroll
        for (int kh = 0; kh < 2; kh++) {
            uint32_t a[4][4], b[2][4];
#pragma unroll
            for (int mt = 0; mt < 4; mt++)
                LDSM_X4(a[mt][0], a[mt][1], a[mt][2], a[mt][3],
                        Abase + a_base + mt * (16 * 80) + kh * 32);
#pragma unroll
            for (int nt = 0; nt < 2; nt++)
                LDSM_X4T(b[nt][0], b[nt][1], b[nt][2], b[nt][3],
                         Bbase + b_off[nt] + kh * 4096);
#pragma unroll
            for (int mt = 0; mt < 4; mt++) {
                MMA16816(acc[mt][0], a[mt], b[0][0], b[0][1]);
                MMA16816(acc[mt][1], a[mt], b[0][2], b[0][3]);
                MMA16816(acc[mt][2], a[mt], b[1][0], b[1][1]);
                MMA16816(acc[mt][3], a[mt], b[1][2], b[1][3]);
            }
        }
    }

    const int er = lane >> 2, ec = (lane & 3) * 2;
    const size_t outz = (size_t)blockIdx.z * N_DIM * L_DIM;
#pragma unroll
    for (int mt = 0; mt < 4; mt++) {
#pragma unroll
        for (int j = 0; j < 4; j++) {
            size_t base = outz + (size_t)(m0 + wm + mt * 16 + er) * L_DIM + (n0 + wn + j * 8 + ec);
            if (OutF) {
                *(float2*)&OutF[base]             = make_float2(acc[mt][j][0], acc[mt][j][1]);
                *(float2*)&OutF[base + 8 * L_DIM] = make_float2(acc[mt][j][2], acc[mt][j][3]);
            } else if (OutH) {
                bf16 h0, l0, h1, l1;
                split1(acc[mt][j][0], h0, l0); split1(acc[mt][j][1], h1, l1);
                *(__nv_bfloat162*)&OutH[base] = __nv_bfloat162(h0, h1);
                *(__nv_bfloat162*)&OutL[base] = __nv_bfloat162(l0, l1);
                split1(acc[mt][j][2], h0, l0); split1(acc[mt][j][3], h1, l1);
                *(__nv_bfloat162*)&OutH[base + 8 * L_DIM] = __nv_bfloat162(h0, h1);
                *(__nv_bfloat162*)&OutL[base + 8 * L_DIM] = __nv_bfloat162(l0, l1);
            } else {
                __half2 v;
                v.x = __float2half_rn(acc[mt][j][0]); v.y = __float2half_rn(acc[mt][j][1]);
                *(__half2*)&Out16[base] = v;
                v.x = __float2half_rn(acc[mt][j][2]); v.y = __float2half_rn(acc[mt][j][3]);
                *(__half2*)&Out16[base + 8 * L_DIM] = v;
            }
        }
    }
}

// ---------------------------------------------------------------------------
// Prep (closed-form, fp16 single outputs)
// ---------------------------------------------------------------------------
#define PW_WB_OFF 0
#define PW_WC_OFF (192 * 65)
#define PW_P_OFF  (PW_WC_OFF + 64 * 128)
#define PW_K_OFF  (PW_P_OFF + 64 * 65)
#define PW_SMEM   ((PW_K_OFF + 64) * 4)

__global__ __launch_bounds__(256) void prep_weights(
    const float* __restrict__ Ar, const float* __restrict__ Ai,
    const float* __restrict__ Ew,
    __half* __restrict__ wb16, __half* __restrict__ wc16)
{
    extern __shared__ float sm[];
    float* sWb = sm + PW_WB_OFF;
    float* sWc = sm + PW_WC_OFF;
    float* sP  = sm + PW_P_OFF;
    float* sK  = sm + PW_K_OFF;

    const int n = blockIdx.x;
    const int tid = threadIdx.x;
    const int s = tid & 63;
    const int dg = tid >> 6;

    const float a = Ar[n * 64 + s], w = Ai[n * 64 + s], E = Ew[n * 64 + s];
    const float er = expf(a);
    const float lr = er * cosf(w), li = er * sinf(w);

#pragma unroll
    for (int dd = 0; dd < 16; dd++) {
        const int d = dg * 16 + dd;
        const float fd = (float)d;
        const float p  = expf(fd * a);
        const float cr = p * cosf(fd * w);
        const float ci = p * sinf(fd * w);
        sWc[(63 - d) * 128 + 2 * s]     = cr;
        sWc[(63 - d) * 128 + 2 * s + 1] = ci;
        sP[d * 65 + s] = E * cr;
        const float cr1 = cr * lr - ci * li;
        const float ci1 = cr * li + ci * lr;
        sWb[(64 + 2 * s) * 65 + d] = E * cr1;
        sWb[(65 + 2 * s) * 65 + d] = -E * ci1;
    }
    __syncthreads();
    if (tid < 64) {
        float acc = 0.f;
#pragma unroll
        for (int q = 0; q < 64; q++) acc += sP[tid * 65 + q];
        sK[tid] = acc;
    }
    __syncthreads();
    for (int i = tid; i < 64 * 64; i += 256) {
        int k = i >> 6, t = i & 63;
        sWb[k * 65 + t] = (t >= k) ? sK[t - k] : 0.f;
    }
    __syncthreads();
    {
        __half* dh = wb16 + (size_t)n * 192 * 64;
        for (int i = tid; i < 192 * 64; i += 256) {
            int r = i >> 6, t = i & 63;
            dh[i] = __float2half_rn(sWb[r * 65 + t]);
        }
    }
    {
        __half* dh = wc16 + (size_t)n * 64 * 128;
        for (int i = tid; i < 64 * 128; i += 256)
            dh[i] = __float2half_rn(sWc[i]);
    }
}

// ---------------------------------------------------------------------------
// FUSED middle kernel, fp16 operands, 105KB smem -> 2 CTAs/SM.
//   phase 1: Cc = x @ Wc (2 chunks) -> H panels fp16
//   phase 2: 4-segment parallel scan (in-place, fp16 storage, fp32 math)
//   phase 3: y = x @ WbToeplitz + H @ WbBasis (6 chunks) -> bf16 split out
// ---------------------------------------------------------------------------
#define FK_PANEL   10320
#define FK_PX_OFF  0                         // 2 panels (x k0-31, k32-63)
#define FK_PH_OFF  (2 * FK_PANEL)            // 4 panels (H mode cols 0-31..96-127)
#define FK_WC_OFF  (6 * FK_PANEL)            // 16384 B
#define FK_WB_OFF  (FK_WC_OFF + 16384)       // 24576 B
#define FK_END_OFF (FK_WB_OFF + 24576)       // seg end states 2048 B
#define FK_SMEM    (FK_END_OFF + 2048)       // 104928 B

__global__ __launch_bounds__(256, 2) void fused_mid(
    const __half* __restrict__ X16,
    const __half* __restrict__ Wc16, const __half* __restrict__ Wb16,
    const float* __restrict__ Ar, const float* __restrict__ Ai,
    bf16* __restrict__ Yh, bf16* __restrict__ Yl)
{
    extern __shared__ char smem[];
    const uint32_t sb = smem_u32(smem);
    const int tid  = threadIdx.x;
    const int lane = tid & 31, wid = tid >> 5;
    const int bb = blockIdx.x;
    const int n  = blockIdx.y;
    const size_t chain = (size_t)bb * N_DIM + n;

    // ---- group 0: x + Wc ------------------------------------------------
    {
        const __half* src = X16 + chain * L_DIM;
        for (int q = tid; q < 1024; q += 256) {
            int j = q >> 3, c = q & 7;
            uint32_t dst = sb + FK_PX_OFF + (uint32_t)(c >> 2) * FK_PANEL
                         + j * 80 + (c & 3) * 16;
            cpa16(dst, src + (size_t)j * 64 + c * 8);
        }
    }
    {
        const __half* src = Wc16 + (size_t)n * 64 * 128;
        for (int q = tid; q < 1024; q += 256) {
            int r = q >> 4, c = q & 15;
            int cp = (c & 8) | ((c ^ (r & 7)) & 7);
            cpa16(sb + FK_WC_OFF + r * 256 + cp * 16,
                  src + (size_t)r * 128 + c * 8);
        }
    }
    CP_COMMIT();
    // ---- group 1: Wb (waited only before phase 3) ------------------------
    {
        const __half* src = Wb16 + (size_t)n * 192 * 64;
        for (int q = tid; q < 1536; q += 256) {
            int r = q >> 3, c = q & 7;
            int cp = c ^ (r & 7);
            cpa16(sb + FK_WB_OFF + r * 128 + cp * 16,
                  src + (size_t)r * 64 + c * 8);
        }
    }
    CP_COMMIT();
    CP_WAIT1();
    __syncthreads();

    // ---- phase 1: contrib MMAs (2 chunks) --------------------------------
    const int wm = (wid >> 2) * 64;
    const int wn128 = (wid & 3) * 32;
    const uint32_t a_base = (uint32_t)(wm + (lane & 15)) * 80 + ((lane >> 4) * 16);
    uint32_t b_off[2];
#pragma unroll
    for (int nt = 0; nt < 2; nt++) {
        int g  = (wn128 >> 3) + nt * 2 + (lane >> 4);
        int gp = (g & 8) | ((g ^ (lane & 7)) & 7);
        b_off[nt] = (uint32_t)(lane & 15) * 256 + gp * 16;
    }

    {
        float acc[4][4][4];
#pragma unroll
        for (int mt = 0; mt < 4; mt++)
#pragma unroll
            for (int j = 0; j < 4; j++)
#pragma unroll
                for (int r = 0; r < 4; r++) acc[mt][j][r] = 0.f;

#pragma unroll
        for (int cl = 0; cl < 2; cl++) {
            const uint32_t Apan = sb + FK_PX_OFF + (uint32_t)cl * FK_PANEL;
            const uint32_t Bk = sb + FK_WC_OFF + (uint32_t)cl * 8192;
#pragma unroll
            for (int kh = 0; kh < 2; kh++) {
                uint32_t a[4][4], b[2][4];
#pragma unroll
                for (int mt = 0; mt < 4; mt++)
                    LDSM_X4(a[mt][0], a[mt][1], a[mt][2], a[mt][3],
                            Apan + a_base + mt * (16 * 80) + kh * 32);
#pragma unroll
                for (int nt = 0; nt < 2; nt++)
                    LDSM_X4T(b[nt][0], b[nt][1], b[nt][2], b[nt][3],
                             Bk + b_off[nt] + kh * 4096);
#pragma unroll
                for (int mt = 0; mt < 4; mt++) {
                    MMA16816H(acc[mt][0], a[mt], b[0][0], b[0][1]);
                    MMA16816H(acc[mt][1], a[mt], b[0][2], b[0][3]);
                    MMA16816H(acc[mt][2], a[mt], b[1][0], b[1][1]);
                    MMA16816H(acc[mt][3], a[mt], b[1][2], b[1][3]);
                }
            }
        }

        const int er = lane >> 2, ec = (lane & 3) * 2;
#pragma unroll
        for (int mt = 0; mt < 4; mt++) {
#pragma unroll
            for (int jj = 0; jj < 4; jj++) {
                int row = wm + mt * 16 + er;
                int col = wn128 + jj * 8 + ec;
                uint32_t po = (uint32_t)(col >> 5) * FK_PANEL + (uint32_t)(col & 31) * 2;
                char* hb = smem + FK_PH_OFF + po;
                __half2 v;
                v.x = __float2half_rn(acc[mt][jj][0]); v.y = __float2half_rn(acc[mt][jj][1]);
                *(__half2*)(hb + row * 80) = v;
                v.x = __float2half_rn(acc[mt][jj][2]); v.y = __float2half_rn(acc[mt][jj][3]);
                *(__half2*)(hb + (row + 8) * 80) = v;
            }
        }
    }
    __syncthreads();

    // ---- phase 2: 4-segment parallel scan --------------------------------
    {
        const int s = tid & 63;
        const int g = tid >> 6;
        const float a = Ar[n * 64 + s], w = Ai[n * 64 + s];
        const float p64 = expf(64.f * a);
        const float c64 = p64 * cosf(64.f * w), s64 = p64 * sinf(64.f * w);
        const int col = 2 * s;
        char* hbase = smem + FK_PH_OFF + (uint32_t)(col >> 5) * FK_PANEL + (uint32_t)(col & 31) * 2;
        float* se = (float*)(smem + FK_END_OFF);
        const int j0 = g * 32;

        float hr = 0.f, hi = 0.f;
#pragma unroll 8
        for (int jj = 0; jj < 32; jj++) {
            const int j = j0 + jj;
            __half2 cv = *(__half2*)(hbase + j * 80);
            float cr = __half2float(cv.x);
            float ci = __half2float(cv.y);
            __half2 st2;
            st2.x = __float2half_rn(hr); st2.y = __float2half_rn(hi);
            *(__half2*)(hbase + j * 80) = st2;
            float nr = c64 * hr - s64 * hi + cr;
            float ni = c64 * hi + s64 * hr + ci;
            hr = nr; hi = ni;
        }
        se[(g * 64 + s) * 2]     = hr;
        se[(g * 64 + s) * 2 + 1] = hi;
        __syncthreads();

        if (g > 0) {
            float pr = 0.f, pi = 0.f;
            for (int q = 0; q < g; q++) {
                float e = (float)(g - 1 - q);
                float pw = expf(2048.f * e * a);
                float cc = pw * cosf(2048.f * e * w), ss = pw * sinf(2048.f * e * w);
                float er_ = se[(q * 64 + s) * 2], ei_ = se[(q * 64 + s) * 2 + 1];
                pr += cc * er_ - ss * ei_;
                pi += cc * ei_ + ss * er_;
            }
            float vr = pr, vi = pi;
#pragma unroll 8
            for (int jj = 0; jj < 32; jj++) {
                const int j = j0 + jj;
                __half2 cv = *(__half2*)(hbase + j * 80);
                float sr = __half2float(cv.x) + vr;
                float si = __half2float(cv.y) + vi;
                __half2 st2;
                st2.x = __float2half_rn(sr); st2.y = __float2half_rn(si);
                *(__half2*)(hbase + j * 80) = st2;
                float nvr = c64 * vr - s64 * vi;
                float nvi = c64 * vi + s64 * vr;
                vr = nvr; vi = nvi;
            }
        }
    }
    CP_WAIT_ALL();
    __syncthreads();

    // ---- phase 3: conv MMAs (6 chunks) -----------------------------------
    {
        const int wn = (wid & 3) * 16;
        float acc[4][2][4];
#pragma unroll
        for (int mt = 0; mt < 4; mt++)
#pragma unroll
            for (int j = 0; j < 2; j++)
#pragma unroll
                for (int r = 0; r < 4; r++) acc[mt][j][r] = 0.f;

#pragma unroll
        for (int cl = 0; cl < 6; cl++) {
            const uint32_t Apan = (cl < 2)
                ? sb + FK_PX_OFF + (uint32_t)cl * FK_PANEL
                : sb + FK_PH_OFF + (uint32_t)(cl - 2) * FK_PANEL;
            const uint32_t Bbase = sb + FK_WB_OFF + (uint32_t)cl * 4096;
#pragma unroll
            for (int kh = 0; kh < 2; kh++) {
                uint32_t a[4][4], b[4];
#pragma unroll
                for (int mt = 0; mt < 4; mt++)
                    LDSM_X4(a[mt][0], a[mt][1], a[mt][2], a[mt][3],
                            Apan + a_base + mt * (16 * 80) + kh * 32);
                {
                    int krow = kh * 16 + (lane & 15);
                    int g = (wn >> 3) + (lane >> 4);
                    uint32_t boff = (uint32_t)krow * 128 + (uint32_t)(((g ^ (krow & 7)) & 7) * 16);
                    LDSM_X4T(b[0], b[1], b[2], b[3], Bbase + boff);
                }
#pragma unroll
                for (int mt = 0; mt < 4; mt++) {
                    MMA16816H(acc[mt][0], a[mt], b[0], b[1]);
                    MMA16816H(acc[mt][1], a[mt], b[2], b[3]);
                }
            }
        }

        const int er = lane >> 2, ec = (lane & 3) * 2;
        bf16* yhp = Yh + chain * L_DIM;
        bf16* ylp = Yl + chain * L_DIM;
#pragma unroll
        for (int mt = 0; mt < 4; mt++) {
#pragma unroll
            for (int j = 0; j < 2; j++) {
                int row0 = wm + mt * 16 + er;
                int tcol = wn + j * 8 + ec;
                size_t b0 = (size_t)row0 * 64 + tcol;
                bf16 h0, l0, h1, l1;
                split1(acc[mt][j][0], h0, l0); split1(acc[mt][j][1], h1, l1);
                *(__nv_bfloat162*)&yhp[b0] = __nv_bfloat162(h0, h1);
                *(__nv_bfloat162*)&ylp[b0] = __nv_bfloat162(l0, l1);
                size_t b1 = (size_t)(row0 + 8) * 64 + tcol;
                split1(acc[mt][j][2], h0, l0); split1(acc[mt][j][3], h1, l1);
                *(__nv_bfloat162*)&yhp[b1] = __nv_bfloat162(h0, h1);
                *(__nv_bfloat162*)&ylp[b1] = __nv_bfloat162(l0, l1);
            }
        }
    }
}

// ---------------------------------------------------------------------------
extern "C" void kernel_launch(void* const* d_in, const int* in_sizes, int n_in,
                              void* d_out, int out_size)
{
    const float* inp = (const float*)d_in[0];  // [B, C, L]
    const float* ar  = (const float*)d_in[1];  // [N, S]
    const float* ai  = (const float*)d_in[2];  // [N, S]
    const float* Bm  = (const float*)d_in[3];  // [N, C]
    const float* Cm  = (const float*)d_in[4];  // [C, N]
    const float* E   = (const float*)d_in[5];  // [N, S]
    float* out = (float*)d_out;                // [B, C, L]

    bf16 *inh, *inl, *yh, *yl, *bh, *bl, *ch, *cl;
    __half *x16, *wb16, *wc16;
    cudaGetSymbolAddress((void**)&inh,  g_inh);
    cudaGetSymbolAddress((void**)&inl,  g_inl);
    cudaGetSymbolAddress((void**)&x16,  g_x16);
    cudaGetSymbolAddress((void**)&yh,   g_yh);
    cudaGetSymbolAddress((void**)&yl,   g_yl);
    cudaGetSymbolAddress((void**)&bh,   g_bh);
    cudaGetSymbolAddress((void**)&bl,   g_bl);
    cudaGetSymbolAddress((void**)&ch,   g_ch);
    cudaGetSymbolAddress((void**)&cl,   g_cl);
    cudaGetSymbolAddress((void**)&wb16, g_wb16);
    cudaGetSymbolAddress((void**)&wc16, g_wc16);

    cudaFuncSetAttribute(hgemm,        cudaFuncAttributeMaxDynamicSharedMemorySize, GEMM_SMEM);
    cudaFuncSetAttribute(prep_weights, cudaFuncAttributeMaxDynamicSharedMemorySize, PW_SMEM);
    cudaFuncSetAttribute(fused_mid,    cudaFuncAttributeMaxDynamicSharedMemorySize, FK_SMEM);

    split_all<<<SPLIT_GRID, 256>>>(inp, Bm, Cm, inh, inl, bh, bl, ch, cl);
    prep_weights<<<N_DIM, 256, PW_SMEM>>>(ar, ai, E, wb16, wc16);

    dim3 gg(L_DIM / 128, N_DIM / 128, B_SZ);
    hgemm<<<gg, 256, GEMM_SMEM>>>(bh, bl, inh, inl,
                                  nullptr, nullptr, nullptr, x16);   // x = B@input (fp16 out)

    fused_mid<<<dim3(B_SZ, N_DIM), 256, FK_SMEM>>>(x16, wc16, wb16, ar, ai, yh, yl);

    hgemm<<<gg, 256, GEMM_SMEM>>>(ch, cl, yh, yl,
                                  out, nullptr, nullptr, nullptr);   // out = C@y
}

// round 17
// speedup vs baseline: 2.4992x; 1.9316x over previous
#include <cuda_runtime.h>
#include <cuda_bf16.h>
#include <cuda_fp16.h>
#include <cstdint>
#include <math.h>

#define B_SZ   4
#define C_DIM  512
#define N_DIM  512
#define S_DIM  64
#define L_DIM  8192
#define NCHK   128

typedef __nv_bfloat16 bf16;

// ---------------------------------------------------------------------------
// Scratch (allocation-free rule: __device__ globals)
// ---------------------------------------------------------------------------
__device__ __align__(128) __half g_in16[(size_t)B_SZ * C_DIM * L_DIM];
__device__ __align__(128) __half g_x16 [(size_t)B_SZ * N_DIM * L_DIM];
__device__ __align__(128) __half g_y16 [(size_t)B_SZ * N_DIM * L_DIM];
__device__ __align__(128) __half g_bm16[C_DIM * N_DIM];
__device__ __align__(128) __half g_cm16[C_DIM * N_DIM];
__device__ __align__(128) __half g_wb16[(size_t)N_DIM * 192 * 64];
__device__ __align__(128) __half g_wc16[(size_t)N_DIM * 64 * 128];

// ---------------------------------------------------------------------------
// Helpers (base PTX only)
// ---------------------------------------------------------------------------
__device__ __forceinline__ uint32_t smem_u32(const void* p) {
    uint32_t a;
    asm("{ .reg .u64 t; cvta.to.shared.u64 t, %1; cvt.u32.u64 %0, t; }" : "=r"(a) : "l"(p));
    return a;
}
__device__ __forceinline__ void cpa16(uint32_t d, const void* s) {
    asm volatile("cp.async.cg.shared.global [%0], [%1], 16;" :: "r"(d), "l"(s));
}
#define CP_COMMIT()   asm volatile("cp.async.commit_group;" ::: "memory")
#define CP_WAIT2()    asm volatile("cp.async.wait_group 2;"  ::: "memory")
#define CP_WAIT1()    asm volatile("cp.async.wait_group 1;"  ::: "memory")
#define CP_WAIT_ALL() asm volatile("cp.async.wait_group 0;" ::: "memory")

#define LDSM_X4(r0,r1,r2,r3,addr) \
    asm volatile("ldmatrix.sync.aligned.m8n8.x4.shared.b16 {%0,%1,%2,%3}, [%4];" \
        : "=r"(r0), "=r"(r1), "=r"(r2), "=r"(r3) : "r"(addr))
#define LDSM_X4T(r0,r1,r2,r3,addr) \
    asm volatile("ldmatrix.sync.aligned.m8n8.x4.trans.shared.b16 {%0,%1,%2,%3}, [%4];" \
        : "=r"(r0), "=r"(r1), "=r"(r2), "=r"(r3) : "r"(addr))

#define MMA16816H(d, a, b0v, b1v) \
    asm volatile("mma.sync.aligned.m16n8k16.row.col.f32.f16.f16.f32 " \
        "{%0,%1,%2,%3}, {%4,%5,%6,%7}, {%8,%9}, {%0,%1,%2,%3};" \
        : "+f"((d)[0]), "+f"((d)[1]), "+f"((d)[2]), "+f"((d)[3]) \
        : "r"((a)[0]), "r"((a)[1]), "r"((a)[2]), "r"((a)[3]), "r"(b0v), "r"(b1v))

// ---------------------------------------------------------------------------
// Combined split pre-pass (input + Bm + Cm -> fp16 single)
// ---------------------------------------------------------------------------
#define SPLIT_IN_BLOCKS  (B_SZ * C_DIM * L_DIM / 1024)   // 16384
#define SPLIT_W_BLOCKS   (C_DIM * N_DIM / 1024)          // 256
#define SPLIT_GRID       (SPLIT_IN_BLOCKS + 2 * SPLIT_W_BLOCKS)

__global__ __launch_bounds__(256) void split_all(
    const float* __restrict__ inp, const float* __restrict__ Bm, const float* __restrict__ Cm,
    __half* __restrict__ in16, __half* __restrict__ bm16, __half* __restrict__ cm16)
{
    const int blk = blockIdx.x;
    const float* src;
    __half* dst;
    int base;
    if (blk < SPLIT_IN_BLOCKS) {
        src = inp; dst = in16; base = blk;
    } else if (blk < SPLIT_IN_BLOCKS + SPLIT_W_BLOCKS) {
        src = Bm;  dst = bm16; base = blk - SPLIT_IN_BLOCKS;
    } else {
        src = Cm;  dst = cm16; base = blk - SPLIT_IN_BLOCKS - SPLIT_W_BLOCKS;
    }
    int i = (base * 256 + threadIdx.x) * 4;
    float4 v = *(const float4*)(src + i);
    __half2 a, b;
    a.x = __float2half_rn(v.x); a.y = __float2half_rn(v.y);
    b.x = __float2half_rn(v.z); b.y = __float2half_rn(v.w);
    ((__half2*)(dst + i))[0] = a;
    ((__half2*)(dst + i))[1] = b;
}

// ---------------------------------------------------------------------------
// fp16 HMMA GEMM: Out[b] = W(512x512) @ X[b](512x8192), single precision.
// Same tile/pipeline structure as the proven bf16-split hgemm, K chunks 48->16.
// Out: fp32 (OutF) or fp16 (Out16).
// ---------------------------------------------------------------------------
#define STAGE   18432
#define A_BYTES 10240
#define NCH16   16
#define GEMM_SMEM (4 * STAGE)

__global__ __launch_bounds__(256, 2) void hgemm16(
    const __half* __restrict__ A,
    const __half* __restrict__ B0,
    float* __restrict__ OutF, __half* __restrict__ Out16)
{
    extern __shared__ char smem[];
    const uint32_t sb = smem_u32(smem);
    const int tid  = threadIdx.x;
    const int lane = tid & 31, wid = tid >> 5;
    const int n0 = blockIdx.x * 128;
    const int m0 = blockIdx.y * 128;
    const __half* B = B0 + (size_t)blockIdx.z * C_DIM * L_DIM;

    const int am = tid >> 2, ac = tid & 3;
    const int bk = tid >> 4, bc = tid & 15;

    auto load_stage = [&](int cl, int st) {
        if (cl < NCH16) {
            const int k0 = cl << 5;
            const uint32_t s0 = sb + (uint32_t)st * STAGE;
            cpa16(s0 + am * 80 + ac * 16,
                  A + (size_t)(m0 + am) * C_DIM + k0 + ac * 8);
            cpa16(s0 + (am + 64) * 80 + ac * 16,
                  A + (size_t)(m0 + am + 64) * C_DIM + k0 + ac * 8);
            {
                int c1 = (bc & 8) | ((bc ^ (bk & 7)) & 7);
                cpa16(s0 + A_BYTES + bk * 256 + c1 * 16,
                      B + (size_t)(k0 + bk) * L_DIM + n0 + bc * 8);
                int k2 = bk + 16;
                int c2 = (bc & 8) | ((bc ^ (k2 & 7)) & 7);
                cpa16(s0 + A_BYTES + k2 * 256 + c2 * 16,
                      B + (size_t)(k0 + k2) * L_DIM + n0 + bc * 8);
            }
        }
        CP_COMMIT();
    };

    const int wm = (wid >> 2) * 64;
    const int wn = (wid & 3) * 32;
    const uint32_t a_base = (uint32_t)(wm + (lane & 15)) * 80 + ((lane >> 4) * 16);
    uint32_t b_off[2];
#pragma unroll
    for (int nt = 0; nt < 2; nt++) {
        int g  = (wn >> 3) + nt * 2 + (lane >> 4);
        int gp = (g & 8) | ((g ^ (lane & 7)) & 7);
        b_off[nt] = (uint32_t)(lane & 15) * 256 + gp * 16;
    }

    float acc[4][4][4];
#pragma unroll
    for (int mt = 0; mt < 4; mt++)
#pragma unroll
        for (int j = 0; j < 4; j++)
#pragma unroll
            for (int r = 0; r < 4; r++) acc[mt][j][r] = 0.f;

    load_stage(0, 0); load_stage(1, 1); load_stage(2, 2);

    for (int c = 0; c < NCH16; c++) {
        CP_WAIT2();
        __syncthreads();
        load_stage(c + 3, (c + 3) & 3);

        const uint32_t Abase = sb + (uint32_t)(c & 3) * STAGE;
        const uint32_t Bbase = Abase + A_BYTES;
#pragma unroll
        for (int kh = 0; kh < 2; kh++) {
            uint32_t a[4][4], b[2][4];
#pragma unroll
            for (int mt = 0; mt < 4; mt++)
                LDSM_X4(a[mt][0], a[mt][1], a[mt][2], a[mt][3],
                        Abase + a_base + mt * (16 * 80) + kh * 32);
#pragma unroll
            for (int nt = 0; nt < 2; nt++)
                LDSM_X4T(b[nt][0], b[nt][1], b[nt][2], b[nt][3],
                         Bbase + b_off[nt] + kh * 4096);
#pragma unroll
            for (int mt = 0; mt < 4; mt++) {
                MMA16816H(acc[mt][0], a[mt], b[0][0], b[0][1]);
                MMA16816H(acc[mt][1], a[mt], b[0][2], b[0][3]);
                MMA16816H(acc[mt][2], a[mt], b[1][0], b[1][1]);
                MMA16816H(acc[mt][3], a[mt], b[1][2], b[1][3]);
            }
        }
    }

    const int er = lane >> 2, ec = (lane & 3) * 2;
    const size_t outz = (size_t)blockIdx.z * N_DIM * L_DIM;
#pragma unroll
    for (int mt = 0; mt < 4; mt++) {
#pragma unroll
        for (int j = 0; j < 4; j++) {
            size_t base = outz + (size_t)(m0 + wm + mt * 16 + er) * L_DIM + (n0 + wn + j * 8 + ec);
            if (OutF) {
                *(float2*)&OutF[base]             = make_float2(acc[mt][j][0], acc[mt][j][1]);
                *(float2*)&OutF[base + 8 * L_DIM] = make_float2(acc[mt][j][2], acc[mt][j][3]);
            } else {
                __half2 v;
                v.x = __float2half_rn(acc[mt][j][0]); v.y = __float2half_rn(acc[mt][j][1]);
                *(__half2*)&Out16[base] = v;
                v.x = __float2half_rn(acc[mt][j][2]); v.y = __float2half_rn(acc[mt][j][3]);
                *(__half2*)&Out16[base + 8 * L_DIM] = v;
            }
        }
    }
}

// ---------------------------------------------------------------------------
// Prep (closed-form, fp16 outputs) — proven 20us
// ---------------------------------------------------------------------------
#define PW_WB_OFF 0
#define PW_WC_OFF (192 * 65)
#define PW_P_OFF  (PW_WC_OFF + 64 * 128)
#define PW_K_OFF  (PW_P_OFF + 64 * 65)
#define PW_SMEM   ((PW_K_OFF + 64) * 4)

__global__ __launch_bounds__(256) void prep_weights(
    const float* __restrict__ Ar, const float* __restrict__ Ai,
    const float* __restrict__ Ew,
    __half* __restrict__ wb16, __half* __restrict__ wc16)
{
    extern __shared__ float sm[];
    float* sWb = sm + PW_WB_OFF;
    float* sWc = sm + PW_WC_OFF;
    float* sP  = sm + PW_P_OFF;
    float* sK  = sm + PW_K_OFF;

    const int n = blockIdx.x;
    const int tid = threadIdx.x;
    const int s = tid & 63;
    const int dg = tid >> 6;

    const float a = Ar[n * 64 + s], w = Ai[n * 64 + s], E = Ew[n * 64 + s];
    const float er = expf(a);
    const float lr = er * cosf(w), li = er * sinf(w);

#pragma unroll
    for (int dd = 0; dd < 16; dd++) {
        const int d = dg * 16 + dd;
        const float fd = (float)d;
        const float p  = expf(fd * a);
        const float cr = p * cosf(fd * w);
        const float ci = p * sinf(fd * w);
        sWc[(63 - d) * 128 + 2 * s]     = cr;
        sWc[(63 - d) * 128 + 2 * s + 1] = ci;
        sP[d * 65 + s] = E * cr;
        const float cr1 = cr * lr - ci * li;
        const float ci1 = cr * li + ci * lr;
        sWb[(64 + 2 * s) * 65 + d] = E * cr1;
        sWb[(65 + 2 * s) * 65 + d] = -E * ci1;
    }
    __syncthreads();
    if (tid < 64) {
        float acc = 0.f;
#pragma unroll
        for (int q = 0; q < 64; q++) acc += sP[tid * 65 + q];
        sK[tid] = acc;
    }
    __syncthreads();
    for (int i = tid; i < 64 * 64; i += 256) {
        int k = i >> 6, t = i & 63;
        sWb[k * 65 + t] = (t >= k) ? sK[t - k] : 0.f;
    }
    __syncthreads();
    {
        __half* dh = wb16 + (size_t)n * 192 * 64;
        for (int i = tid; i < 192 * 64; i += 256) {
            int r = i >> 6, t = i & 63;
            dh[i] = __float2half_rn(sWb[r * 65 + t]);
        }
    }
    {
        __half* dh = wc16 + (size_t)n * 64 * 128;
        for (int i = tid; i < 64 * 128; i += 256)
            dh[i] = __float2half_rn(sWc[i]);
    }
}

// ---------------------------------------------------------------------------
// FUSED middle kernel (R16 proven, 67.7us), y output now fp16 single.
// ---------------------------------------------------------------------------
#define FK_PANEL   10320
#define FK_PX_OFF  0
#define FK_PH_OFF  (2 * FK_PANEL)
#define FK_WC_OFF  (6 * FK_PANEL)
#define FK_WB_OFF  (FK_WC_OFF + 16384)
#define FK_END_OFF (FK_WB_OFF + 24576)
#define FK_SMEM    (FK_END_OFF + 2048)

__global__ __launch_bounds__(256, 2) void fused_mid(
    const __half* __restrict__ X16,
    const __half* __restrict__ Wc16, const __half* __restrict__ Wb16,
    const float* __restrict__ Ar, const float* __restrict__ Ai,
    __half* __restrict__ Y16)
{
    extern __shared__ char smem[];
    const uint32_t sb = smem_u32(smem);
    const int tid  = threadIdx.x;
    const int lane = tid & 31, wid = tid >> 5;
    const int bb = blockIdx.x;
    const int n  = blockIdx.y;
    const size_t chain = (size_t)bb * N_DIM + n;

    // ---- group 0: x + Wc ------------------------------------------------
    {
        const __half* src = X16 + chain * L_DIM;
        for (int q = tid; q < 1024; q += 256) {
            int j = q >> 3, c = q & 7;
            uint32_t dst = sb + FK_PX_OFF + (uint32_t)(c >> 2) * FK_PANEL
                         + j * 80 + (c & 3) * 16;
            cpa16(dst, src + (size_t)j * 64 + c * 8);
        }
    }
    {
        const __half* src = Wc16 + (size_t)n * 64 * 128;
        for (int q = tid; q < 1024; q += 256) {
            int r = q >> 4, c = q & 15;
            int cp = (c & 8) | ((c ^ (r & 7)) & 7);
            cpa16(sb + FK_WC_OFF + r * 256 + cp * 16,
                  src + (size_t)r * 128 + c * 8);
        }
    }
    CP_COMMIT();
    // ---- group 1: Wb (waited only before phase 3) ------------------------
    {
        const __half* src = Wb16 + (size_t)n * 192 * 64;
        for (int q = tid; q < 1536; q += 256) {
            int r = q >> 3, c = q & 7;
            int cp = c ^ (r & 7);
            cpa16(sb + FK_WB_OFF + r * 128 + cp * 16,
                  src + (size_t)r * 64 + c * 8);
        }
    }
    CP_COMMIT();
    CP_WAIT1();
    __syncthreads();

    // ---- phase 1: contrib MMAs (2 chunks) --------------------------------
    const int wm = (wid >> 2) * 64;
    const int wn128 = (wid & 3) * 32;
    const uint32_t a_base = (uint32_t)(wm + (lane & 15)) * 80 + ((lane >> 4) * 16);
    uint32_t b_off[2];
#pragma unroll
    for (int nt = 0; nt < 2; nt++) {
        int g  = (wn128 >> 3) + nt * 2 + (lane >> 4);
        int gp = (g & 8) | ((g ^ (lane & 7)) & 7);
        b_off[nt] = (uint32_t)(lane & 15) * 256 + gp * 16;
    }

    {
        float acc[4][4][4];
#pragma unroll
        for (int mt = 0; mt < 4; mt++)
#pragma unroll
            for (int j = 0; j < 4; j++)
#pragma unroll
                for (int r = 0; r < 4; r++) acc[mt][j][r] = 0.f;

#pragma unroll
        for (int cl = 0; cl < 2; cl++) {
            const uint32_t Apan = sb + FK_PX_OFF + (uint32_t)cl * FK_PANEL;
            const uint32_t Bk = sb + FK_WC_OFF + (uint32_t)cl * 8192;
#pragma unroll
            for (int kh = 0; kh < 2; kh++) {
                uint32_t a[4][4], b[2][4];
#pragma unroll
                for (int mt = 0; mt < 4; mt++)
                    LDSM_X4(a[mt][0], a[mt][1], a[mt][2], a[mt][3],
                            Apan + a_base + mt * (16 * 80) + kh * 32);
#pragma unroll
                for (int nt = 0; nt < 2; nt++)
                    LDSM_X4T(b[nt][0], b[nt][1], b[nt][2], b[nt][3],
                             Bk + b_off[nt] + kh * 4096);
#pragma unroll
                for (int mt = 0; mt < 4; mt++) {
                    MMA16816H(acc[mt][0], a[mt], b[0][0], b[0][1]);
                    MMA16816H(acc[mt][1], a[mt], b[0][2], b[0][3]);
                    MMA16816H(acc[mt][2], a[mt], b[1][0], b[1][1]);
                    MMA16816H(acc[mt][3], a[mt], b[1][2], b[1][3]);
                }
            }
        }

        const int er = lane >> 2, ec = (lane & 3) * 2;
#pragma unroll
        for (int mt = 0; mt < 4; mt++) {
#pragma unroll
            for (int jj = 0; jj < 4; jj++) {
                int row = wm + mt * 16 + er;
                int col = wn128 + jj * 8 + ec;
                uint32_t po = (uint32_t)(col >> 5) * FK_PANEL + (uint32_t)(col & 31) * 2;
                char* hb = smem + FK_PH_OFF + po;
                __half2 v;
                v.x = __float2half_rn(acc[mt][jj][0]); v.y = __float2half_rn(acc[mt][jj][1]);
                *(__half2*)(hb + row * 80) = v;
                v.x = __float2half_rn(acc[mt][jj][2]); v.y = __float2half_rn(acc[mt][jj][3]);
                *(__half2*)(hb + (row + 8) * 80) = v;
            }
        }
    }
    __syncthreads();

    // ---- phase 2: 4-segment parallel scan --------------------------------
    {
        const int s = tid & 63;
        const int g = tid >> 6;
        const float a = Ar[n * 64 + s], w = Ai[n * 64 + s];
        const float p64 = expf(64.f * a);
        const float c64 = p64 * cosf(64.f * w), s64 = p64 * sinf(64.f * w);
        const int col = 2 * s;
        char* hbase = smem + FK_PH_OFF + (uint32_t)(col >> 5) * FK_PANEL + (uint32_t)(col & 31) * 2;
        float* se = (float*)(smem + FK_END_OFF);
        const int j0 = g * 32;

        float hr = 0.f, hi = 0.f;
#pragma unroll 8
        for (int jj = 0; jj < 32; jj++) {
            const int j = j0 + jj;
            __half2 cv = *(__half2*)(hbase + j * 80);
            float cr = __half2float(cv.x);
            float ci = __half2float(cv.y);
            __half2 st2;
            st2.x = __float2half_rn(hr); st2.y = __float2half_rn(hi);
            *(__half2*)(hbase + j * 80) = st2;
            float nr = c64 * hr - s64 * hi + cr;
            float ni = c64 * hi + s64 * hr + ci;
            hr = nr; hi = ni;
        }
        se[(g * 64 + s) * 2]     = hr;
        se[(g * 64 + s) * 2 + 1] = hi;
        __syncthreads();

        if (g > 0) {
            float pr = 0.f, pi = 0.f;
            for (int q = 0; q < g; q++) {
                float e = (float)(g - 1 - q);
                float pw = expf(2048.f * e * a);
                float cc = pw * cosf(2048.f * e * w), ss = pw * sinf(2048.f * e * w);
                float er_ = se[(q * 64 + s) * 2], ei_ = se[(q * 64 + s) * 2 + 1];
                pr += cc * er_ - ss * ei_;
                pi += cc * ei_ + ss * er_;
            }
            float vr = pr, vi = pi;
#pragma unroll 8
            for (int jj = 0; jj < 32; jj++) {
                const int j = j0 + jj;
                __half2 cv = *(__half2*)(hbase + j * 80);
                float sr = __half2float(cv.x) + vr;
                float si = __half2float(cv.y) + vi;
                __half2 st2;
                st2.x = __float2half_rn(sr); st2.y = __float2half_rn(si);
                *(__half2*)(hbase + j * 80) = st2;
                float nvr = c64 * vr - s64 * vi;
                float nvi = c64 * vi + s64 * vr;
                vr = nvr; vi = nvi;
            }
        }
    }
    CP_WAIT_ALL();
    __syncthreads();

    // ---- phase 3: conv MMAs (6 chunks), fp16 y out -----------------------
    {
        const int wn = (wid & 3) * 16;
        float acc[4][2][4];
#pragma unroll
        for (int mt = 0; mt < 4; mt++)
#pragma unroll
            for (int j = 0; j < 2; j++)
#pragma unroll
                for (int r = 0; r < 4; r++) acc[mt][j][r] = 0.f;

#pragma unroll
        for (int cl = 0; cl < 6; cl++) {
            const uint32_t Apan = (cl < 2)
                ? sb + FK_PX_OFF + (uint32_t)cl * FK_PANEL
                : sb + FK_PH_OFF + (uint32_t)(cl - 2) * FK_PANEL;
            const uint32_t Bbase = sb + FK_WB_OFF + (uint32_t)cl * 4096;
#pragma unroll
            for (int kh = 0; kh < 2; kh++) {
                uint32_t a[4][4], b[4];
#pragma unroll
                for (int mt = 0; mt < 4; mt++)
                    LDSM_X4(a[mt][0], a[mt][1], a[mt][2], a[mt][3],
                            Apan + a_base + mt * (16 * 80) + kh * 32);
                {
                    int krow = kh * 16 + (lane & 15);
                    int g = (wn >> 3) + (lane >> 4);
                    uint32_t boff = (uint32_t)krow * 128 + (uint32_t)(((g ^ (krow & 7)) & 7) * 16);
                    LDSM_X4T(b[0], b[1], b[2], b[3], Bbase + boff);
                }
#pragma unroll
                for (int mt = 0; mt < 4; mt++) {
                    MMA16816H(acc[mt][0], a[mt], b[0], b[1]);
                    MMA16816H(acc[mt][1], a[mt], b[2], b[3]);
                }
            }
        }

        const int er = lane >> 2, ec = (lane & 3) * 2;
        __half* yp = Y16 + chain * L_DIM;
#pragma unroll
        for (int mt = 0; mt < 4; mt++) {
#pragma unroll
            for (int j = 0; j < 2; j++) {
                int row0 = wm + mt * 16 + er;
                int tcol = wn + j * 8 + ec;
                size_t b0 = (size_t)row0 * 64 + tcol;
                __half2 v;
                v.x = __float2half_rn(acc[mt][j][0]); v.y = __float2half_rn(acc[mt][j][1]);
                *(__half2*)&yp[b0] = v;
                size_t b1 = (size_t)(row0 + 8) * 64 + tcol;
                v.x = __float2half_rn(acc[mt][j][2]); v.y = __float2half_rn(acc[mt][j][3]);
                *(__half2*)&yp[b1] = v;
            }
        }
    }
}

// ---------------------------------------------------------------------------
extern "C" void kernel_launch(void* const* d_in, const int* in_sizes, int n_in,
                              void* d_out, int out_size)
{
    const float* inp = (const float*)d_in[0];  // [B, C, L]
    const float* ar  = (const float*)d_in[1];  // [N, S]
    const float* ai  = (const float*)d_in[2];  // [N, S]
    const float* Bm  = (const float*)d_in[3];  // [N, C]
    const float* Cm  = (const float*)d_in[4];  // [C, N]
    const float* E   = (const float*)d_in[5];  // [N, S]
    float* out = (float*)d_out;                // [B, C, L]

    __half *in16, *x16, *y16, *bm16, *cm16, *wb16, *wc16;
    cudaGetSymbolAddress((void**)&in16, g_in16);
    cudaGetSymbolAddress((void**)&x16,  g_x16);
    cudaGetSymbolAddress((void**)&y16,  g_y16);
    cudaGetSymbolAddress((void**)&bm16, g_bm16);
    cudaGetSymbolAddress((void**)&cm16, g_cm16);
    cudaGetSymbolAddress((void**)&wb16, g_wb16);
    cudaGetSymbolAddress((void**)&wc16, g_wc16);

    cudaFuncSetAttribute(hgemm16,      cudaFuncAttributeMaxDynamicSharedMemorySize, GEMM_SMEM);
    cudaFuncSetAttribute(prep_weights, cudaFuncAttributeMaxDynamicSharedMemorySize, PW_SMEM);
    cudaFuncSetAttribute(fused_mid,    cudaFuncAttributeMaxDynamicSharedMemorySize, FK_SMEM);

    split_all<<<SPLIT_GRID, 256>>>(inp, Bm, Cm, in16, bm16, cm16);
    prep_weights<<<N_DIM, 256, PW_SMEM>>>(ar, ai, E, wb16, wc16);

    dim3 gg(L_DIM / 128, N_DIM / 128, B_SZ);
    hgemm16<<<gg, 256, GEMM_SMEM>>>(bm16, in16, nullptr, x16);      // x = B@input (fp16)

    fused_mid<<<dim3(B_SZ, N_DIM), 256, FK_SMEM>>>(x16, wc16, wb16, ar, ai, y16);

    hgemm16<<<gg, 256, GEMM_SMEM>>>(cm16, y16, out, nullptr);       // out = C@y (fp32)
}